// round 4
// baseline (speedup 1.0000x reference)
#include <cuda_runtime.h>
#include <cuda_bf16.h>
#include <cuda_fp16.h>

#define ELEMF 64
#define NBRF  32
#define COUT  128
#define KTOT  160
#define EPS   1e-5f
#define E_MAX 1600000
#define N_MAX 50000

// row stride for bf16 smem tiles: 168 bf16 = 336 bytes (84 banks = 20 mod 32 -> conflict-free LDSM)
#define RSTRIDE_B 336
#define TILE_BYTES (128 * RSTRIDE_B)   // 43008

// ---------------- scratch (device globals; no allocation allowed) -----------
__device__ __half g_hidden2[(size_t)E_MAX * COUT]; // pre-BN1 hidden (E,128) fp16
__device__ float g_sums[(size_t)N_MAX * ELEMF];    // segment sums (N,64)
__device__ float g_stats1[2 * COUT];               // sum / sumsq per hidden col
__device__ float g_stats2[2 * ELEMF];              // sum / sumsq per summed col
// Pre-split W: 2 bufs (hi, lo), each [128 n][160 k (stride 168)] bf16
__device__ unsigned char g_Bsw[2 * TILE_BYTES];
// Pre-split atom features: (N, 64) bf16 hi / lo (128B rows)
__device__ __nv_bfloat16 g_atomHi[(size_t)N_MAX * ELEMF];
__device__ __nv_bfloat16 g_atomLo[(size_t)N_MAX * ELEMF];

// ---------------- helpers -----------------------------------------------------
__device__ __forceinline__ unsigned smem_u32(const void* p) {
    unsigned a;
    asm("{ .reg .u64 t; cvta.to.shared.u64 t, %1; cvt.u32.u64 %0, t; }"
        : "=r"(a) : "l"(p));
    return a;
}
__device__ __forceinline__ unsigned bf2(float a, float b) {  // elem0=a, elem1=b
    unsigned r;
    asm("cvt.rn.bf16x2.f32 %0, %1, %2;" : "=r"(r) : "f"(b), "f"(a));
    return r;
}
__device__ __forceinline__ void ldsm4(unsigned addr, unsigned& r0, unsigned& r1,
                                      unsigned& r2, unsigned& r3) {
    asm volatile("ldmatrix.sync.aligned.m8n8.x4.shared.b16 {%0,%1,%2,%3}, [%4];"
                 : "=r"(r0), "=r"(r1), "=r"(r2), "=r"(r3) : "r"(addr));
}
__device__ __forceinline__ void mma16816(float* d, const unsigned* a,
                                         unsigned b0, unsigned b1) {
    asm volatile("mma.sync.aligned.m16n8k16.row.col.f32.bf16.bf16.f32 "
                 "{%0,%1,%2,%3}, {%4,%5,%6,%7}, {%8,%9}, {%0,%1,%2,%3};"
                 : "+f"(d[0]), "+f"(d[1]), "+f"(d[2]), "+f"(d[3])
                 : "r"(a[0]), "r"(a[1]), "r"(a[2]), "r"(a[3]), "r"(b0), "r"(b1));
}
// split 8 fp32 -> hi/lo bf16x2 quads
__device__ __forceinline__ void split8(float4 v0, float4 v1, uint4& hi, uint4& lo) {
    hi.x = bf2(v0.x, v0.y); hi.y = bf2(v0.z, v0.w);
    hi.z = bf2(v1.x, v1.y); hi.w = bf2(v1.z, v1.w);
    float l0 = v0.x - __uint_as_float(hi.x << 16);
    float l1 = v0.y - __uint_as_float(hi.x & 0xFFFF0000u);
    float l2 = v0.z - __uint_as_float(hi.y << 16);
    float l3 = v0.w - __uint_as_float(hi.y & 0xFFFF0000u);
    float l4 = v1.x - __uint_as_float(hi.z << 16);
    float l5 = v1.y - __uint_as_float(hi.z & 0xFFFF0000u);
    float l6 = v1.z - __uint_as_float(hi.w << 16);
    float l7 = v1.w - __uint_as_float(hi.w & 0xFFFF0000u);
    lo.x = bf2(l0, l1); lo.y = bf2(l2, l3);
    lo.z = bf2(l4, l5); lo.w = bf2(l6, l7);
}

// ---------------- kernels ----------------------------------------------------
// launch index 0
__global__ void zero_kernel(int n_sums) {
    int i = blockIdx.x * blockDim.x + threadIdx.x;
    int stride = gridDim.x * blockDim.x;
    for (int j = i; j < n_sums; j += stride) g_sums[j] = 0.f;
    if (i < 2 * COUT)  g_stats1[i] = 0.f;
    if (i < 2 * ELEMF) g_stats2[i] = 0.f;
}

// launch index 1: split W (160x128 fp32, [k][n]) into hi/lo bf16 [n][k] tiles.
__global__ void wsplit_kernel(const float* __restrict__ W) {
    int i = blockIdx.x * blockDim.x + threadIdx.x;
    if (i >= 2 * 128 * KTOT) return;
    int k   = i % KTOT;
    int n   = (i / KTOT) & 127;
    int buf = i / (128 * KTOT);
    float w = W[k * COUT + n];
    __nv_bfloat16 h = __float2bfloat16_rn(w);
    unsigned short out;
    if (buf == 0) {
        out = *reinterpret_cast<unsigned short*>(&h);
    } else {
        float lo = w - __bfloat162float(h);
        __nv_bfloat16 l = __float2bfloat16_rn(lo);
        out = *reinterpret_cast<unsigned short*>(&l);
    }
    *reinterpret_cast<unsigned short*>(g_Bsw + buf * TILE_BYTES + n * RSTRIDE_B + k * 2) = out;
}

// launch index 2: split atom table (N,64) into bf16 hi/lo
__global__ void asplit_kernel(const float* __restrict__ atom, int total) {
    int i = blockIdx.x * blockDim.x + threadIdx.x;
    if (i >= total) return;
    float v = atom[i];
    __nv_bfloat16 h = __float2bfloat16_rn(v);
    g_atomHi[i] = h;
    g_atomLo[i] = __float2bfloat16_rn(v - __bfloat162float(h));
}

// launch index 3 (ncu captures this one): persistent HMMA gather-GEMM.
// Tile = 128 edges x 128 outputs. hidden(fp16) = Ah@Bh + Al@Bh + Ah@Bl + bias.
__global__ __launch_bounds__(256, 1) void gemm_tc_kernel(
    const float* __restrict__ nbrfea,
    const int* __restrict__ selfIdx, const int* __restrict__ nbrIdx,
    const float* __restrict__ bias, int E, int nTiles)
{
    extern __shared__ char smem[];
    const unsigned sbase = smem_u32(smem);

    const int AH_OFF  = 0;
    const int AL_OFF  = TILE_BYTES;
    const int BH_OFF  = 2 * TILE_BYTES;
    const int BL_OFF  = 3 * TILE_BYTES;
    const int BIAS_OFF = 4 * TILE_BYTES;          // 512 B
    const int STAT_OFF = BIAS_OFF + 512;          // 1024 B

    const int tid = threadIdx.x, wid = tid >> 5, lane = tid & 31;

    {
        const uint4* src = reinterpret_cast<const uint4*>(g_Bsw);
        uint4* dst = reinterpret_cast<uint4*>(smem + BH_OFF);
        for (int i = tid; i < 2 * TILE_BYTES / 16; i += 256) dst[i] = src[i];
    }
    if (tid < COUT) reinterpret_cast<float*>(smem + BIAS_OFF)[tid] = bias[tid];
    reinterpret_cast<float*>(smem + STAT_OFF)[tid] = 0.f;
    __syncthreads();

    // warp tiling: 2 m-warps x 4 n-warps; warp tile = m64 x n32
    const int wm = (wid >> 2) * 64;
    const int wn = (wid & 3) * 32;
    const unsigned lane_off = (lane & 15) * RSTRIDE_B + ((lane >> 4) << 4);

    const int cb = wn + 2 * (lane & 3);
    float bc0[4], bc1[4];
#pragma unroll
    for (int j = 0; j < 4; ++j) {
        bc0[j] = reinterpret_cast<float*>(smem + BIAS_OFF)[cb + 8 * j];
        bc1[j] = reinterpret_cast<float*>(smem + BIAS_OFF)[cb + 8 * j + 1];
    }

    const unsigned aoff[3] = {sbase + AH_OFF, sbase + AL_OFF, sbase + AH_OFF};
    const unsigned boff[3] = {sbase + BH_OFF, sbase + BH_OFF, sbase + BL_OFF};
    float* sstat = reinterpret_cast<float*>(smem + STAT_OFF);

    for (int tile = blockIdx.x; tile < nTiles; tile += gridDim.x) {
        const int eb = tile * 128;
        __syncthreads();   // previous LDSM done before overwrite

        // ----- gather (copy-only for atom segments) -----
        {
            const int r = tid >> 1, h = tid & 1;
            const int e = eb + r;
            const bool v = (e < E);
            const int si = v ? selfIdx[e] : 0;
            const int ni = v ? nbrIdx[e] : 0;
            char* rowH = smem + AH_OFF + r * RSTRIDE_B;
            char* rowL = smem + AL_OFF + r * RSTRIDE_B;
            const uint4 Zu = make_uint4(0, 0, 0, 0);
            // self hi/lo: k bytes [h*64, h*64+64); nbr hi/lo: [128 + h*64, ...)
            const uint4* sh = reinterpret_cast<const uint4*>(g_atomHi + (size_t)si * ELEMF) + h * 4;
            const uint4* sl = reinterpret_cast<const uint4*>(g_atomLo + (size_t)si * ELEMF) + h * 4;
            const uint4* nh = reinterpret_cast<const uint4*>(g_atomHi + (size_t)ni * ELEMF) + h * 4;
            const uint4* nl = reinterpret_cast<const uint4*>(g_atomLo + (size_t)ni * ELEMF) + h * 4;
#pragma unroll
            for (int g2 = 0; g2 < 4; ++g2) {
                uint4 a0 = v ? sh[g2] : Zu;
                uint4 a1 = v ? sl[g2] : Zu;
                uint4 a2 = v ? nh[g2] : Zu;
                uint4 a3 = v ? nl[g2] : Zu;
                *reinterpret_cast<uint4*>(rowH + h * 64 + g2 * 16) = a0;
                *reinterpret_cast<uint4*>(rowL + h * 64 + g2 * 16) = a1;
                *reinterpret_cast<uint4*>(rowH + 128 + h * 64 + g2 * 16) = a2;
                *reinterpret_cast<uint4*>(rowL + 128 + h * 64 + g2 * 16) = a3;
            }
            // edge features: split per-edge (16 cols per thread)
            {
                const float4 Z = make_float4(0.f, 0.f, 0.f, 0.f);
                const float* src = nbrfea + (size_t)e * NBRF + h * 16;
                const int kb = 256 + h * 32;
#pragma unroll
                for (int g2 = 0; g2 < 2; ++g2) {
                    float4 v0 = v ? reinterpret_cast<const float4*>(src)[g2 * 2]     : Z;
                    float4 v1 = v ? reinterpret_cast<const float4*>(src)[g2 * 2 + 1] : Z;
                    uint4 hi, lo;
                    split8(v0, v1, hi, lo);
                    *reinterpret_cast<uint4*>(rowH + kb + g2 * 16) = hi;
                    *reinterpret_cast<uint4*>(rowL + kb + g2 * 16) = lo;
                }
            }
        }
        __syncthreads();

        // ----- HMMA: 3 passes (Ah,Bh)(Al,Bh)(Ah,Bl), K=160 each -----
        float d[4][4][4];
#pragma unroll
        for (int i = 0; i < 4; ++i)
#pragma unroll
            for (int j = 0; j < 4; ++j)
#pragma unroll
                for (int q = 0; q < 4; ++q) d[i][j][q] = 0.f;

#pragma unroll
        for (int p = 0; p < 3; ++p) {
            const unsigned abase = aoff[p] + wm * RSTRIDE_B + lane_off;
            const unsigned bbase = boff[p] + wn * RSTRIDE_B + lane_off;
#pragma unroll
            for (int kk = 0; kk < 10; ++kk) {
                const unsigned kb = kk * 32;
                unsigned a[4][4];
#pragma unroll
                for (int i = 0; i < 4; ++i)
                    ldsm4(abase + i * 16 * RSTRIDE_B + kb,
                          a[i][0], a[i][1], a[i][2], a[i][3]);
                unsigned u0, u1, u2, u3, w0, w1, w2, w3;
                ldsm4(bbase + kb, u0, u1, u2, u3);
                ldsm4(bbase + 16 * RSTRIDE_B + kb, w0, w1, w2, w3);
#pragma unroll
                for (int i = 0; i < 4; ++i) {
                    mma16816(d[i][0], a[i], u0, u2);
                    mma16816(d[i][1], a[i], u1, u3);
                    mma16816(d[i][2], a[i], w0, w2);
                    mma16816(d[i][3], a[i], w1, w3);
                }
            }
        }

        // ----- epilogue: bias, fp16 store, BN1 stats -----
#pragma unroll
        for (int i = 0; i < 4; ++i) {
            const int e1 = eb + wm + 16 * i + (lane >> 2);
            const int e2 = e1 + 8;
            const bool v1 = (e1 < E), v2 = (e2 < E);
            __half* out1 = g_hidden2 + (size_t)e1 * COUT + cb;
            __half* out2 = g_hidden2 + (size_t)e2 * COUT + cb;
#pragma unroll
            for (int j = 0; j < 4; ++j) {
                float v00 = d[i][j][0] + bc0[j];
                float v01 = d[i][j][1] + bc1[j];
                float v10 = d[i][j][2] + bc0[j];
                float v11 = d[i][j][3] + bc1[j];
                if (v1) *reinterpret_cast<__half2*>(out1 + 8 * j) = __floats2half2_rn(v00, v01);
                if (v2) *reinterpret_cast<__half2*>(out2 + 8 * j) = __floats2half2_rn(v10, v11);
                float s0 = (v1 ? v00 : 0.f) + (v2 ? v10 : 0.f);
                float s1 = (v1 ? v01 : 0.f) + (v2 ? v11 : 0.f);
                float q0 = (v1 ? v00 * v00 : 0.f) + (v2 ? v10 * v10 : 0.f);
                float q1 = (v1 ? v01 * v01 : 0.f) + (v2 ? v11 * v11 : 0.f);
                d[i][j][0] = s0; d[i][j][1] = s1; d[i][j][2] = q0; d[i][j][3] = q1;
            }
        }
#pragma unroll
        for (int j = 0; j < 4; ++j) {
            float s0 = d[0][j][0] + d[1][j][0] + d[2][j][0] + d[3][j][0];
            float s1 = d[0][j][1] + d[1][j][1] + d[2][j][1] + d[3][j][1];
            float q0 = d[0][j][2] + d[1][j][2] + d[2][j][2] + d[3][j][2];
            float q1 = d[0][j][3] + d[1][j][3] + d[2][j][3] + d[3][j][3];
#pragma unroll
            for (int ofs = 4; ofs <= 16; ofs <<= 1) {
                s0 += __shfl_xor_sync(0xFFFFFFFF, s0, ofs);
                s1 += __shfl_xor_sync(0xFFFFFFFF, s1, ofs);
                q0 += __shfl_xor_sync(0xFFFFFFFF, q0, ofs);
                q1 += __shfl_xor_sync(0xFFFFFFFF, q1, ofs);
            }
            if (lane < 4) {
                const int c = wn + 2 * lane + 8 * j;
                atomicAdd(&sstat[c], s0);
                atomicAdd(&sstat[c + 1], s1);
                atomicAdd(&sstat[COUT + c], q0);
                atomicAdd(&sstat[COUT + c + 1], q1);
            }
        }
    }

    __syncthreads();
    atomicAdd(&g_stats1[tid], sstat[tid]);
}

__device__ __forceinline__ float softplus_fast(float x) {
    // max(x,0) + log(1 + exp(-|x|)) with fast intrinsics
    return fmaxf(x, 0.f) + __logf(1.f + __expf(-fabsf(x)));
}

// launch index 4: BN1 apply, sigmoid*softplus, segment-sum (sorted self idx)
__global__ __launch_bounds__(256) void msg_segsum_kernel(
    const int* __restrict__ selfIdx,
    const float* __restrict__ gamma1, const float* __restrict__ beta1,
    int E, float invE)
{
    __shared__ float s1[128], t1[128];
    const int tid = threadIdx.x;
    if (tid < 128) {
        float mean = g_stats1[tid] * invE;
        float var  = g_stats1[128 + tid] * invE - mean * mean;
        float r = rsqrtf(var + EPS);
        float g = gamma1[tid];
        s1[tid] = g * r;
        t1[tid] = beta1[tid] - g * mean * r;
    }
    __syncthreads();

    const int c = tid & 63;
    const int lane = tid >> 6;
    const int CHUNK = 64;
    long gl = (long)blockIdx.x * 4 + lane;
    int es = (int)(gl * CHUNK);
    if (es >= E) return;
    int ee = min(es + CHUNK, E);

    const float sf = s1[c],      tf = t1[c];
    const float sc = s1[64 + c], tc = t1[64 + c];

    int cur = selfIdx[es];
    float accv = 0.f;
    for (int e = es; e < ee; ++e) {
        int a = selfIdx[e];
        if (a != cur) {
            atomicAdd(&g_sums[(size_t)cur * ELEMF + c], accv);
            cur = a; accv = 0.f;
        }
        const __half* hp = g_hidden2 + (size_t)e * COUT;
        float f = fmaf(sf, __half2float(hp[c]), tf);
        float g = fmaf(sc, __half2float(hp[64 + c]), tc);
        float sig = __fdividef(1.f, 1.f + __expf(-f));
        accv = fmaf(sig, softplus_fast(g), accv);
    }
    atomicAdd(&g_sums[(size_t)cur * ELEMF + c], accv);
}

// launch index 5
__global__ __launch_bounds__(256) void stats2_kernel(int Nn) {
    __shared__ float rs[4][64];
    __shared__ float rq[4][64];
    const int tid = threadIdx.x;
    const int c = tid & 63, rl = tid >> 6;
    float s = 0.f, q = 0.f;
    for (int row = blockIdx.x * 4 + rl; row < Nn; row += gridDim.x * 4) {
        float v = g_sums[(size_t)row * ELEMF + c];
        s += v; q += v * v;
    }
    rs[rl][c] = s; rq[rl][c] = q;
    __syncthreads();
    if (tid < 64) {
        float ss = 0.f, qq = 0.f;
#pragma unroll
        for (int r = 0; r < 4; ++r) { ss += rs[r][tid]; qq += rq[r][tid]; }
        atomicAdd(&g_stats2[tid], ss);
        atomicAdd(&g_stats2[64 + tid], qq);
    }
}

// launch index 6 (full precision softplus for the output)
__device__ __forceinline__ float softplusf(float x) {
    return (x > 15.f) ? x : log1pf(expf(x));
}
__global__ __launch_bounds__(256) void out_kernel(
    const float* __restrict__ atom,
    const float* __restrict__ gamma2, const float* __restrict__ beta2,
    float* __restrict__ outp, int Nn, float invN)
{
    __shared__ float s2[64], t2[64];
    const int tid = threadIdx.x;
    if (tid < 64) {
        float mean = g_stats2[tid] * invN;
        float var  = g_stats2[64 + tid] * invN - mean * mean;
        float r = rsqrtf(var + EPS);
        float g = gamma2[tid];
        s2[tid] = g * r;
        t2[tid] = beta2[tid] - g * mean * r;
    }
    __syncthreads();
    const int c = tid & 63, rl = tid >> 6;
    for (int row = blockIdx.x * 4 + rl; row < Nn; row += gridDim.x * 4) {
        size_t idx = (size_t)row * ELEMF + c;
        float v = fmaf(s2[c], g_sums[idx], t2[c]) + atom[idx];
        outp[idx] = softplusf(v);
    }
}

extern "C" void kernel_launch(void* const* d_in, const int* in_sizes, int n_in,
                              void* d_out, int out_size)
{
    const float* atom   = (const float*)d_in[0];
    const float* nbrfea = (const float*)d_in[1];
    const int*   sIdx   = (const int*)d_in[2];
    const int*   nIdx   = (const int*)d_in[3];
    const float* W      = (const float*)d_in[4];
    const float* b      = (const float*)d_in[5];
    const float* gamma1 = (const float*)d_in[6];
    const float* beta1  = (const float*)d_in[7];
    const float* gamma2 = (const float*)d_in[8];
    const float* beta2  = (const float*)d_in[9];
    float* outp = (float*)d_out;

    const int Nn = in_sizes[0] / ELEMF;
    const int E  = in_sizes[2];
    const int nTiles = (E + 127) / 128;

    const int SMEM_BYTES = 4 * TILE_BYTES + 512 + 1024;   // 173568
    cudaFuncSetAttribute(gemm_tc_kernel,
                         cudaFuncAttributeMaxDynamicSharedMemorySize, SMEM_BYTES);
    int sms = 148;
    cudaDeviceGetAttribute(&sms, cudaDevAttrMultiProcessorCount, 0);
    int grid = sms < nTiles ? sms : nTiles;

    zero_kernel<<<2048, 256>>>(Nn * ELEMF);
    wsplit_kernel<<<(2 * 128 * KTOT + 255) / 256, 256>>>(W);
    asplit_kernel<<<(Nn * ELEMF + 255) / 256, 256>>>(atom, Nn * ELEMF);
    gemm_tc_kernel<<<grid, 256, SMEM_BYTES>>>(nbrfea, sIdx, nIdx, b, E, nTiles);

    int lanes = (E + 63) / 64;
    int msg_blocks = (lanes + 3) / 4;
    msg_segsum_kernel<<<msg_blocks, 256>>>(sIdx, gamma1, beta1, E, 1.f / (float)E);

    stats2_kernel<<<592, 256>>>(Nn);

    int out_blocks = (Nn + 3) / 4;
    out_kernel<<<out_blocks, 256>>>(atom, gamma2, beta2, outp, Nn, 1.f / (float)Nn);
}

// round 5
// speedup vs baseline: 1.8714x; 1.8714x over previous
#include <cuda_runtime.h>
#include <cuda_bf16.h>
#include <cuda_fp16.h>

#define ELEMF 64
#define NBRF  32
#define COUT  128
#define KTOT  160
#define EPS   1e-5f
#define E_MAX 1600000
#define N_MAX 50000

// row stride for bf16 smem tiles: 168 bf16 = 336 bytes (84 banks = 20 mod 32 -> conflict-free LDSM)
#define RSTRIDE_B 336
#define TILE_BYTES (128 * RSTRIDE_B)   // 43008

// ---------------- scratch (device globals; no allocation allowed) -----------
__device__ __half g_hidden2[(size_t)E_MAX * COUT]; // pre-BN1 hidden (E,128) fp16
__device__ float g_sums[(size_t)N_MAX * ELEMF];    // segment sums (N,64)
__device__ float g_stats1[2 * COUT];               // sum / sumsq per hidden col
__device__ float g_stats2[2 * ELEMF];              // sum / sumsq per summed col
// Pre-split W: 2 bufs (hi, lo), each [128 n][160 k (stride 168)] bf16
__device__ unsigned char g_Bsw[2 * TILE_BYTES];
// Pre-split atom features: (N, 64) bf16 hi / lo
__device__ __nv_bfloat16 g_atomHi[(size_t)N_MAX * ELEMF];
__device__ __nv_bfloat16 g_atomLo[(size_t)N_MAX * ELEMF];

// ---------------- helpers -----------------------------------------------------
__device__ __forceinline__ unsigned smem_u32(const void* p) {
    unsigned a;
    asm("{ .reg .u64 t; cvta.to.shared.u64 t, %1; cvt.u32.u64 %0, t; }"
        : "=r"(a) : "l"(p));
    return a;
}
__device__ __forceinline__ unsigned bf2(float a, float b) {
    unsigned r;
    asm("cvt.rn.bf16x2.f32 %0, %1, %2;" : "=r"(r) : "f"(b), "f"(a));
    return r;
}
__device__ __forceinline__ void ldsm4(unsigned addr, unsigned& r0, unsigned& r1,
                                      unsigned& r2, unsigned& r3) {
    asm volatile("ldmatrix.sync.aligned.m8n8.x4.shared.b16 {%0,%1,%2,%3}, [%4];"
                 : "=r"(r0), "=r"(r1), "=r"(r2), "=r"(r3) : "r"(addr));
}
__device__ __forceinline__ void mma16816(float* d, const unsigned* a,
                                         unsigned b0, unsigned b1) {
    asm volatile("mma.sync.aligned.m16n8k16.row.col.f32.bf16.bf16.f32 "
                 "{%0,%1,%2,%3}, {%4,%5,%6,%7}, {%8,%9}, {%0,%1,%2,%3};"
                 : "+f"(d[0]), "+f"(d[1]), "+f"(d[2]), "+f"(d[3])
                 : "r"(a[0]), "r"(a[1]), "r"(a[2]), "r"(a[3]), "r"(b0), "r"(b1));
}
__device__ __forceinline__ void split8(float4 v0, float4 v1, uint4& hi, uint4& lo) {
    hi.x = bf2(v0.x, v0.y); hi.y = bf2(v0.z, v0.w);
    hi.z = bf2(v1.x, v1.y); hi.w = bf2(v1.z, v1.w);
    float l0 = v0.x - __uint_as_float(hi.x << 16);
    float l1 = v0.y - __uint_as_float(hi.x & 0xFFFF0000u);
    float l2 = v0.z - __uint_as_float(hi.y << 16);
    float l3 = v0.w - __uint_as_float(hi.y & 0xFFFF0000u);
    float l4 = v1.x - __uint_as_float(hi.z << 16);
    float l5 = v1.y - __uint_as_float(hi.z & 0xFFFF0000u);
    float l6 = v1.z - __uint_as_float(hi.w << 16);
    float l7 = v1.w - __uint_as_float(hi.w & 0xFFFF0000u);
    lo.x = bf2(l0, l1); lo.y = bf2(l2, l3);
    lo.z = bf2(l4, l5); lo.w = bf2(l6, l7);
}

// ---------------- kernels ----------------------------------------------------
__global__ void zero_kernel(int n_sums) {
    int i = blockIdx.x * blockDim.x + threadIdx.x;
    int stride = gridDim.x * blockDim.x;
    for (int j = i; j < n_sums; j += stride) g_sums[j] = 0.f;
    if (i < 2 * COUT)  g_stats1[i] = 0.f;
    if (i < 2 * ELEMF) g_stats2[i] = 0.f;
}

__global__ void wsplit_kernel(const float* __restrict__ W) {
    int i = blockIdx.x * blockDim.x + threadIdx.x;
    if (i >= 2 * 128 * KTOT) return;
    int k   = i % KTOT;
    int n   = (i / KTOT) & 127;
    int buf = i / (128 * KTOT);
    float w = W[k * COUT + n];
    __nv_bfloat16 h = __float2bfloat16_rn(w);
    unsigned short out;
    if (buf == 0) {
        out = *reinterpret_cast<unsigned short*>(&h);
    } else {
        float lo = w - __bfloat162float(h);
        __nv_bfloat16 l = __float2bfloat16_rn(lo);
        out = *reinterpret_cast<unsigned short*>(&l);
    }
    *reinterpret_cast<unsigned short*>(g_Bsw + buf * TILE_BYTES + n * RSTRIDE_B + k * 2) = out;
}

__global__ void asplit_kernel(const float* __restrict__ atom, int total) {
    int i = blockIdx.x * blockDim.x + threadIdx.x;
    if (i >= total) return;
    float v = atom[i];
    __nv_bfloat16 h = __float2bfloat16_rn(v);
    g_atomHi[i] = h;
    g_atomLo[i] = __float2bfloat16_rn(v - __bfloat162float(h));
}

// launch index 3 (ncu captures this): persistent HMMA gather-GEMM, 512 threads.
// 16 warps: 4 m-warps x 4 n-warps, warp tile m32 x n32.
// hidden(fp16) = Ah@Bh + Al@Bh + Ah@Bl + bias; BN1 stats in registers across tiles.
__global__ __launch_bounds__(512, 1) void gemm_tc_kernel(
    const float* __restrict__ nbrfea,
    const int* __restrict__ selfIdx, const int* __restrict__ nbrIdx,
    const float* __restrict__ bias, int E, int nTiles)
{
    extern __shared__ char smem[];
    const unsigned sbase = smem_u32(smem);

    const int AH_OFF  = 0;
    const int AL_OFF  = TILE_BYTES;
    const int BH_OFF  = 2 * TILE_BYTES;
    const int BL_OFF  = 3 * TILE_BYTES;
    const int BIAS_OFF = 4 * TILE_BYTES;          // 512 B
    const int STAT_OFF = BIAS_OFF + 512;          // 1024 B

    const int tid = threadIdx.x, wid = tid >> 5, lane = tid & 31;

    {
        const uint4* src = reinterpret_cast<const uint4*>(g_Bsw);
        uint4* dst = reinterpret_cast<uint4*>(smem + BH_OFF);
        for (int i = tid; i < 2 * TILE_BYTES / 16; i += 512) dst[i] = src[i];
    }
    if (tid < COUT) reinterpret_cast<float*>(smem + BIAS_OFF)[tid] = bias[tid];
    if (tid < 256)  reinterpret_cast<float*>(smem + STAT_OFF)[tid] = 0.f;
    __syncthreads();

    const int wm = (wid >> 2) * 32;              // m-warp row base
    const int wn = (wid & 3) * 32;               // n-warp col base
    const unsigned lane_off = (lane & 15) * RSTRIDE_B + ((lane >> 4) << 4);

    const int cb = wn + 2 * (lane & 3);
    float bc0[4], bc1[4];
#pragma unroll
    for (int j = 0; j < 4; ++j) {
        bc0[j] = reinterpret_cast<float*>(smem + BIAS_OFF)[cb + 8 * j];
        bc1[j] = reinterpret_cast<float*>(smem + BIAS_OFF)[cb + 8 * j + 1];
    }

    const unsigned abaseH = sbase + AH_OFF + wm * RSTRIDE_B + lane_off;
    const unsigned abaseL = sbase + AL_OFF + wm * RSTRIDE_B + lane_off;
    const unsigned bbaseH = sbase + BH_OFF + wn * RSTRIDE_B + lane_off;
    const unsigned bbaseL = sbase + BL_OFF + wn * RSTRIDE_B + lane_off;
    float* sstat = reinterpret_cast<float*>(smem + STAT_OFF);

    // cross-tile BN1 stats (per thread, per column pair)
    float aS0[4] = {0,0,0,0}, aS1[4] = {0,0,0,0};
    float aQ0[4] = {0,0,0,0}, aQ1[4] = {0,0,0,0};

    for (int tile = blockIdx.x; tile < nTiles; tile += gridDim.x) {
        const int eb = tile * 128;
        __syncthreads();   // previous LDSM done before overwrite

        // ----- gather: 4 threads per row -----
        {
            const int r = tid >> 2, q = tid & 3;
            const int e = eb + r;
            const bool v = (e < E);
            const int si = v ? selfIdx[e] : 0;
            const int ni = v ? nbrIdx[e] : 0;
            char* rowH = smem + AH_OFF + r * RSTRIDE_B;
            char* rowL = smem + AL_OFF + r * RSTRIDE_B;
            const uint4 Zu = make_uint4(0, 0, 0, 0);
            const uint4* sh = reinterpret_cast<const uint4*>(g_atomHi + (size_t)si * ELEMF);
            const uint4* sl = reinterpret_cast<const uint4*>(g_atomLo + (size_t)si * ELEMF);
            const uint4* nh = reinterpret_cast<const uint4*>(g_atomHi + (size_t)ni * ELEMF);
            const uint4* nl = reinterpret_cast<const uint4*>(g_atomLo + (size_t)ni * ELEMF);
            // self: bytes [32q, 32q+32); nbr: [128+32q, ...)
            {
                uint4 x0 = v ? sh[q * 2]     : Zu;
                uint4 x1 = v ? sh[q * 2 + 1] : Zu;
                *reinterpret_cast<uint4*>(rowH + 32 * q)      = x0;
                *reinterpret_cast<uint4*>(rowH + 32 * q + 16) = x1;
            }
            {
                uint4 x0 = v ? sl[q * 2]     : Zu;
                uint4 x1 = v ? sl[q * 2 + 1] : Zu;
                *reinterpret_cast<uint4*>(rowL + 32 * q)      = x0;
                *reinterpret_cast<uint4*>(rowL + 32 * q + 16) = x1;
            }
            {
                uint4 x0 = v ? nh[q * 2]     : Zu;
                uint4 x1 = v ? nh[q * 2 + 1] : Zu;
                *reinterpret_cast<uint4*>(rowH + 128 + 32 * q)      = x0;
                *reinterpret_cast<uint4*>(rowH + 128 + 32 * q + 16) = x1;
            }
            {
                uint4 x0 = v ? nl[q * 2]     : Zu;
                uint4 x1 = v ? nl[q * 2 + 1] : Zu;
                *reinterpret_cast<uint4*>(rowL + 128 + 32 * q)      = x0;
                *reinterpret_cast<uint4*>(rowL + 128 + 32 * q + 16) = x1;
            }
            // edge features: 8 cols per thread, split per-edge
            {
                const float4 Z = make_float4(0.f, 0.f, 0.f, 0.f);
                const float* src = nbrfea + (size_t)e * NBRF + q * 8;
                float4 v0 = v ? reinterpret_cast<const float4*>(src)[0] : Z;
                float4 v1 = v ? reinterpret_cast<const float4*>(src)[1] : Z;
                uint4 hi, lo;
                split8(v0, v1, hi, lo);
                *reinterpret_cast<uint4*>(rowH + 256 + 16 * q) = hi;
                *reinterpret_cast<uint4*>(rowL + 256 + 16 * q) = lo;
            }
        }
        __syncthreads();

        // ----- fused HMMA mainloop: per k-step load Ah/Al/Bh/Bl once, 24 MMAs -----
        float d[2][4][4];
#pragma unroll
        for (int i = 0; i < 2; ++i)
#pragma unroll
            for (int j = 0; j < 4; ++j)
#pragma unroll
                for (int q2 = 0; q2 < 4; ++q2) d[i][j][q2] = 0.f;

#pragma unroll
        for (int kk = 0; kk < 10; ++kk) {
            const unsigned kb = kk * 32;
            unsigned ah[2][4], al[2][4];
            ldsm4(abaseH + kb,                  ah[0][0], ah[0][1], ah[0][2], ah[0][3]);
            ldsm4(abaseH + 16 * RSTRIDE_B + kb, ah[1][0], ah[1][1], ah[1][2], ah[1][3]);
            ldsm4(abaseL + kb,                  al[0][0], al[0][1], al[0][2], al[0][3]);
            ldsm4(abaseL + 16 * RSTRIDE_B + kb, al[1][0], al[1][1], al[1][2], al[1][3]);
            unsigned hu0, hu1, hu2, hu3, hw0, hw1, hw2, hw3;
            unsigned lu0, lu1, lu2, lu3, lw0, lw1, lw2, lw3;
            ldsm4(bbaseH + kb,                  hu0, hu1, hu2, hu3);
            ldsm4(bbaseH + 16 * RSTRIDE_B + kb, hw0, hw1, hw2, hw3);
            ldsm4(bbaseL + kb,                  lu0, lu1, lu2, lu3);
            ldsm4(bbaseL + 16 * RSTRIDE_B + kb, lw0, lw1, lw2, lw3);
#pragma unroll
            for (int i = 0; i < 2; ++i) {
                mma16816(d[i][0], ah[i], hu0, hu2);
                mma16816(d[i][1], ah[i], hu1, hu3);
                mma16816(d[i][2], ah[i], hw0, hw2);
                mma16816(d[i][3], ah[i], hw1, hw3);
                mma16816(d[i][0], al[i], hu0, hu2);
                mma16816(d[i][1], al[i], hu1, hu3);
                mma16816(d[i][2], al[i], hw0, hw2);
                mma16816(d[i][3], al[i], hw1, hw3);
                mma16816(d[i][0], ah[i], lu0, lu2);
                mma16816(d[i][1], ah[i], lu1, lu3);
                mma16816(d[i][2], ah[i], lw0, lw2);
                mma16816(d[i][3], ah[i], lw1, lw3);
            }
        }

        // ----- epilogue: bias, fp16 store, register stats -----
#pragma unroll
        for (int i = 0; i < 2; ++i) {
            const int e1 = eb + wm + 16 * i + (lane >> 2);
            const int e2 = e1 + 8;
            const bool v1 = (e1 < E), v2 = (e2 < E);
            __half* out1 = g_hidden2 + (size_t)e1 * COUT + cb;
            __half* out2 = g_hidden2 + (size_t)e2 * COUT + cb;
#pragma unroll
            for (int j = 0; j < 4; ++j) {
                float v00 = d[i][j][0] + bc0[j];
                float v01 = d[i][j][1] + bc1[j];
                float v10 = d[i][j][2] + bc0[j];
                float v11 = d[i][j][3] + bc1[j];
                if (v1) {
                    *reinterpret_cast<__half2*>(out1 + 8 * j) = __floats2half2_rn(v00, v01);
                    aS0[j] += v00; aS1[j] += v01;
                    aQ0[j] += v00 * v00; aQ1[j] += v01 * v01;
                }
                if (v2) {
                    *reinterpret_cast<__half2*>(out2 + 8 * j) = __floats2half2_rn(v10, v11);
                    aS0[j] += v10; aS1[j] += v11;
                    aQ0[j] += v10 * v10; aQ1[j] += v11 * v11;
                }
            }
        }
    }

    // ----- one-shot BN1 stats reduction -----
#pragma unroll
    for (int j = 0; j < 4; ++j) {
#pragma unroll
        for (int ofs = 4; ofs <= 16; ofs <<= 1) {
            aS0[j] += __shfl_xor_sync(0xFFFFFFFF, aS0[j], ofs);
            aS1[j] += __shfl_xor_sync(0xFFFFFFFF, aS1[j], ofs);
            aQ0[j] += __shfl_xor_sync(0xFFFFFFFF, aQ0[j], ofs);
            aQ1[j] += __shfl_xor_sync(0xFFFFFFFF, aQ1[j], ofs);
        }
        if (lane < 4) {
            const int c = wn + 2 * lane + 8 * j;
            atomicAdd(&sstat[c], aS0[j]);
            atomicAdd(&sstat[c + 1], aS1[j]);
            atomicAdd(&sstat[COUT + c], aQ0[j]);
            atomicAdd(&sstat[COUT + c + 1], aQ1[j]);
        }
    }
    __syncthreads();
    if (tid < 256) atomicAdd(&g_stats1[tid], sstat[tid]);
}

__device__ __forceinline__ float softplus_fast(float x) {
    return fmaxf(x, 0.f) + __logf(1.f + __expf(-fabsf(x)));
}

__global__ __launch_bounds__(256) void msg_segsum_kernel(
    const int* __restrict__ selfIdx,
    const float* __restrict__ gamma1, const float* __restrict__ beta1,
    int E, float invE)
{
    __shared__ float s1[128], t1[128];
    const int tid = threadIdx.x;
    if (tid < 128) {
        float mean = g_stats1[tid] * invE;
        float var  = g_stats1[128 + tid] * invE - mean * mean;
        float r = rsqrtf(var + EPS);
        float g = gamma1[tid];
        s1[tid] = g * r;
        t1[tid] = beta1[tid] - g * mean * r;
    }
    __syncthreads();

    const int c = tid & 63;
    const int lane = tid >> 6;
    const int CHUNK = 64;
    long gl = (long)blockIdx.x * 4 + lane;
    int es = (int)(gl * CHUNK);
    if (es >= E) return;
    int ee = min(es + CHUNK, E);

    const float sf = s1[c],      tf = t1[c];
    const float sc = s1[64 + c], tc = t1[64 + c];

    int cur = selfIdx[es];
    float accv = 0.f;
    for (int e = es; e < ee; ++e) {
        int a = selfIdx[e];
        if (a != cur) {
            atomicAdd(&g_sums[(size_t)cur * ELEMF + c], accv);
            cur = a; accv = 0.f;
        }
        const __half* hp = g_hidden2 + (size_t)e * COUT;
        float f = fmaf(sf, __half2float(hp[c]), tf);
        float g = fmaf(sc, __half2float(hp[64 + c]), tc);
        float sig = __fdividef(1.f, 1.f + __expf(-f));
        accv = fmaf(sig, softplus_fast(g), accv);
    }
    atomicAdd(&g_sums[(size_t)cur * ELEMF + c], accv);
}

__global__ __launch_bounds__(256) void stats2_kernel(int Nn) {
    __shared__ float rs[4][64];
    __shared__ float rq[4][64];
    const int tid = threadIdx.x;
    const int c = tid & 63, rl = tid >> 6;
    float s = 0.f, q = 0.f;
    for (int row = blockIdx.x * 4 + rl; row < Nn; row += gridDim.x * 4) {
        float v = g_sums[(size_t)row * ELEMF + c];
        s += v; q += v * v;
    }
    rs[rl][c] = s; rq[rl][c] = q;
    __syncthreads();
    if (tid < 64) {
        float ss = 0.f, qq = 0.f;
#pragma unroll
        for (int r = 0; r < 4; ++r) { ss += rs[r][tid]; qq += rq[r][tid]; }
        atomicAdd(&g_stats2[tid], ss);
        atomicAdd(&g_stats2[64 + tid], qq);
    }
}

__device__ __forceinline__ float softplusf(float x) {
    return (x > 15.f) ? x : log1pf(expf(x));
}
__global__ __launch_bounds__(256) void out_kernel(
    const float* __restrict__ atom,
    const float* __restrict__ gamma2, const float* __restrict__ beta2,
    float* __restrict__ outp, int Nn, float invN)
{
    __shared__ float s2[64], t2[64];
    const int tid = threadIdx.x;
    if (tid < 64) {
        float mean = g_stats2[tid] * invN;
        float var  = g_stats2[64 + tid] * invN - mean * mean;
        float r = rsqrtf(var + EPS);
        float g = gamma2[tid];
        s2[tid] = g * r;
        t2[tid] = beta2[tid] - g * mean * r;
    }
    __syncthreads();
    const int c = tid & 63, rl = tid >> 6;
    for (int row = blockIdx.x * 4 + rl; row < Nn; row += gridDim.x * 4) {
        size_t idx = (size_t)row * ELEMF + c;
        float v = fmaf(s2[c], g_sums[idx], t2[c]) + atom[idx];
        outp[idx] = softplusf(v);
    }
}

extern "C" void kernel_launch(void* const* d_in, const int* in_sizes, int n_in,
                              void* d_out, int out_size)
{
    const float* atom   = (const float*)d_in[0];
    const float* nbrfea = (const float*)d_in[1];
    const int*   sIdx   = (const int*)d_in[2];
    const int*   nIdx   = (const int*)d_in[3];
    const float* W      = (const float*)d_in[4];
    const float* b      = (const float*)d_in[5];
    const float* gamma1 = (const float*)d_in[6];
    const float* beta1  = (const float*)d_in[7];
    const float* gamma2 = (const float*)d_in[8];
    const float* beta2  = (const float*)d_in[9];
    float* outp = (float*)d_out;

    const int Nn = in_sizes[0] / ELEMF;
    const int E  = in_sizes[2];
    const int nTiles = (E + 127) / 128;

    const int SMEM_BYTES = 4 * TILE_BYTES + 512 + 1024;   // 173568
    cudaFuncSetAttribute(gemm_tc_kernel,
                         cudaFuncAttributeMaxDynamicSharedMemorySize, SMEM_BYTES);
    int sms = 148;
    cudaDeviceGetAttribute(&sms, cudaDevAttrMultiProcessorCount, 0);
    int grid = sms < nTiles ? sms : nTiles;

    zero_kernel<<<2048, 256>>>(Nn * ELEMF);
    wsplit_kernel<<<(2 * 128 * KTOT + 255) / 256, 256>>>(W);
    asplit_kernel<<<(Nn * ELEMF + 255) / 256, 256>>>(atom, Nn * ELEMF);
    gemm_tc_kernel<<<grid, 512, SMEM_BYTES>>>(nbrfea, sIdx, nIdx, b, E, nTiles);

    int lanes = (E + 63) / 64;
    int msg_blocks = (lanes + 3) / 4;
    msg_segsum_kernel<<<msg_blocks, 256>>>(sIdx, gamma1, beta1, E, 1.f / (float)E);

    stats2_kernel<<<592, 256>>>(Nn);

    int out_blocks = (Nn + 3) / 4;
    out_kernel<<<out_blocks, 256>>>(atom, gamma2, beta2, outp, Nn, 1.f / (float)Nn);
}

// round 6
// speedup vs baseline: 2.2324x; 1.1929x over previous
#include <cuda_runtime.h>
#include <cuda_fp16.h>

#define ELEMF 64
#define NBRF  32
#define COUT  128
#define KTOT  160
#define EPS   1e-5f
#define E_MAX 1600000
#define N_MAX 50000

// row stride for fp16 smem tiles: 168 halves = 336 bytes (84 banks -> conflict-free LDSM)
#define RSTRIDE_B 336
#define TILE_BYTES (128 * RSTRIDE_B)   // 43008

// ---------------- scratch (device globals; no allocation allowed) -----------
__device__ __half g_hidden2[(size_t)E_MAX * COUT]; // pre-BN1 hidden (E,128) fp16
__device__ float g_sums[(size_t)N_MAX * ELEMF];    // segment sums (N,64)
__device__ float g_stats1[2 * COUT];               // sum / sumsq per hidden col
__device__ float g_stats2[2 * ELEMF];              // sum / sumsq per summed col
__device__ unsigned char g_Wf[TILE_BYTES];         // W fp16, [n][k] rows of 336B
__device__ __half g_atomF[(size_t)N_MAX * ELEMF];  // atom table fp16

// ---------------- helpers -----------------------------------------------------
__device__ __forceinline__ unsigned smem_u32(const void* p) {
    unsigned a;
    asm("{ .reg .u64 t; cvta.to.shared.u64 t, %1; cvt.u32.u64 %0, t; }"
        : "=r"(a) : "l"(p));
    return a;
}
__device__ __forceinline__ void ldsm4(unsigned addr, unsigned& r0, unsigned& r1,
                                      unsigned& r2, unsigned& r3) {
    asm volatile("ldmatrix.sync.aligned.m8n8.x4.shared.b16 {%0,%1,%2,%3}, [%4];"
                 : "=r"(r0), "=r"(r1), "=r"(r2), "=r"(r3) : "r"(addr));
}
__device__ __forceinline__ void mma16816(float* d, const unsigned* a,
                                         unsigned b0, unsigned b1) {
    asm volatile("mma.sync.aligned.m16n8k16.row.col.f32.f16.f16.f32 "
                 "{%0,%1,%2,%3}, {%4,%5,%6,%7}, {%8,%9}, {%0,%1,%2,%3};"
                 : "+f"(d[0]), "+f"(d[1]), "+f"(d[2]), "+f"(d[3])
                 : "r"(a[0]), "r"(a[1]), "r"(a[2]), "r"(a[3]), "r"(b0), "r"(b1));
}
__device__ __forceinline__ unsigned h2pack(float a, float b) {
    __half2 p = __floats2half2_rn(a, b);   // low = a (k ascending), high = b
    return *reinterpret_cast<unsigned*>(&p);
}

// ---------------- kernels ----------------------------------------------------
// launch 0
__global__ void zero_kernel(int n_sums) {
    int i = blockIdx.x * blockDim.x + threadIdx.x;
    int stride = gridDim.x * blockDim.x;
    for (int j = i; j < n_sums; j += stride) g_sums[j] = 0.f;
    if (i < 2 * COUT)  g_stats1[i] = 0.f;
    if (i < 2 * ELEMF) g_stats2[i] = 0.f;
}

// launch 1: W (160x128 fp32 [k][n]) -> fp16 [n][k] rows of 336B
__global__ void wconv_kernel(const float* __restrict__ W) {
    int i = blockIdx.x * blockDim.x + threadIdx.x;
    if (i >= 128 * KTOT) return;
    int k = i % KTOT;
    int n = i / KTOT;
    __half h = __float2half_rn(W[k * COUT + n]);
    *reinterpret_cast<__half*>(g_Wf + n * RSTRIDE_B + k * 2) = h;
}

// launch 2: atom table fp32 -> fp16
__global__ void aconv_kernel(const float* __restrict__ atom, int total) {
    int i = blockIdx.x * blockDim.x + threadIdx.x;
    if (i >= total) return;
    g_atomF[i] = __float2half_rn(atom[i]);
}

// launch 3 (ncu captures this): persistent fp16 HMMA gather-GEMM.
// 256 threads, 8 warps (2m x 4n), warp tile m64 x n32, 2 CTAs/SM.
__global__ __launch_bounds__(256, 2) void gemm_tc_kernel(
    const float* __restrict__ nbrfea,
    const int* __restrict__ selfIdx, const int* __restrict__ nbrIdx,
    const float* __restrict__ bias, int E, int nTiles)
{
    extern __shared__ char smem[];
    const unsigned sbase = smem_u32(smem);

    const int A_OFF    = 0;                       // 43008
    const int B_OFF    = TILE_BYTES;              // 43008
    const int BIAS_OFF = 2 * TILE_BYTES;          // 512 B
    const int STAT_OFF = BIAS_OFF + 512;          // 1024 B

    const int tid = threadIdx.x, wid = tid >> 5, lane = tid & 31;

    // B tile -> smem once
    {
        const uint4* src = reinterpret_cast<const uint4*>(g_Wf);
        uint4* dst = reinterpret_cast<uint4*>(smem + B_OFF);
        for (int i = tid; i < TILE_BYTES / 16; i += 256) dst[i] = src[i];
    }
    if (tid < COUT) reinterpret_cast<float*>(smem + BIAS_OFF)[tid] = bias[tid];
    reinterpret_cast<float*>(smem + STAT_OFF)[tid] = 0.f;
    __syncthreads();

    const int wm = (wid >> 2) * 64;              // 2 m-warps
    const int wn = (wid & 3) * 32;               // 4 n-warps
    const unsigned lane_off = (lane & 15) * RSTRIDE_B + ((lane >> 4) << 4);

    const int cb = wn + 2 * (lane & 3);
    float bc0[4], bc1[4];
#pragma unroll
    for (int j = 0; j < 4; ++j) {
        bc0[j] = reinterpret_cast<float*>(smem + BIAS_OFF)[cb + 8 * j];
        bc1[j] = reinterpret_cast<float*>(smem + BIAS_OFF)[cb + 8 * j + 1];
    }

    const unsigned abase = sbase + A_OFF + wm * RSTRIDE_B + lane_off;
    const unsigned bbase = sbase + B_OFF + wn * RSTRIDE_B + lane_off;
    float* sstat = reinterpret_cast<float*>(smem + STAT_OFF);

    // cross-tile BN1 stats in registers
    float aS0[4] = {0,0,0,0}, aS1[4] = {0,0,0,0};
    float aQ0[4] = {0,0,0,0}, aQ1[4] = {0,0,0,0};

    for (int tile = blockIdx.x; tile < nTiles; tile += gridDim.x) {
        const int eb = tile * 128;
        __syncthreads();   // previous LDSM done before overwrite

        // ----- gather: 2 threads per row (h = half) -----
        {
            const int r = tid >> 1, h = tid & 1;
            const int e = eb + r;
            const bool v = (e < E);
            const int si = v ? selfIdx[e] : 0;
            const int ni = v ? nbrIdx[e] : 0;
            char* rowA = smem + A_OFF + r * RSTRIDE_B;
            const uint4 Zu = make_uint4(0, 0, 0, 0);
            const uint4* sp = reinterpret_cast<const uint4*>(g_atomF + (size_t)si * ELEMF) + h * 4;
            const uint4* np = reinterpret_cast<const uint4*>(g_atomF + (size_t)ni * ELEMF) + h * 4;
#pragma unroll
            for (int g2 = 0; g2 < 4; ++g2) {
                uint4 x0 = v ? sp[g2] : Zu;
                uint4 x1 = v ? np[g2] : Zu;
                *reinterpret_cast<uint4*>(rowA + h * 64 + g2 * 16)       = x0;
                *reinterpret_cast<uint4*>(rowA + 128 + h * 64 + g2 * 16) = x1;
            }
            // edge features: 16 floats -> 16 fp16 per thread
            {
                const float4 Z = make_float4(0.f, 0.f, 0.f, 0.f);
                const float* src = nbrfea + (size_t)e * NBRF + h * 16;
#pragma unroll
                for (int g2 = 0; g2 < 2; ++g2) {
                    float4 v0 = v ? reinterpret_cast<const float4*>(src)[g2 * 2]     : Z;
                    float4 v1 = v ? reinterpret_cast<const float4*>(src)[g2 * 2 + 1] : Z;
                    uint4 o;
                    o.x = h2pack(v0.x, v0.y); o.y = h2pack(v0.z, v0.w);
                    o.z = h2pack(v1.x, v1.y); o.w = h2pack(v1.z, v1.w);
                    *reinterpret_cast<uint4*>(rowA + 256 + h * 32 + g2 * 16) = o;
                }
            }
        }
        __syncthreads();

        // ----- fp16 HMMA mainloop: 6 LDSM + 16 MMA per k-step -----
        float d[4][4][4];
#pragma unroll
        for (int i = 0; i < 4; ++i)
#pragma unroll
            for (int j = 0; j < 4; ++j)
#pragma unroll
                for (int q2 = 0; q2 < 4; ++q2) d[i][j][q2] = 0.f;

#pragma unroll
        for (int kk = 0; kk < 10; ++kk) {
            const unsigned kb = kk * 32;
            unsigned a[4][4];
#pragma unroll
            for (int i = 0; i < 4; ++i)
                ldsm4(abase + i * 16 * RSTRIDE_B + kb,
                      a[i][0], a[i][1], a[i][2], a[i][3]);
            unsigned u0, u1, u2, u3, w0, w1, w2, w3;
            ldsm4(bbase + kb,                  u0, u1, u2, u3);
            ldsm4(bbase + 16 * RSTRIDE_B + kb, w0, w1, w2, w3);
#pragma unroll
            for (int i = 0; i < 4; ++i) {
                mma16816(d[i][0], a[i], u0, u2);
                mma16816(d[i][1], a[i], u1, u3);
                mma16816(d[i][2], a[i], w0, w2);
                mma16816(d[i][3], a[i], w1, w3);
            }
        }

        // ----- epilogue: bias, fp16 store, register stats -----
#pragma unroll
        for (int i = 0; i < 4; ++i) {
            const int e1 = eb + wm + 16 * i + (lane >> 2);
            const int e2 = e1 + 8;
            const bool v1 = (e1 < E), v2 = (e2 < E);
            __half* out1 = g_hidden2 + (size_t)e1 * COUT + cb;
            __half* out2 = g_hidden2 + (size_t)e2 * COUT + cb;
#pragma unroll
            for (int j = 0; j < 4; ++j) {
                float v00 = d[i][j][0] + bc0[j];
                float v01 = d[i][j][1] + bc1[j];
                float v10 = d[i][j][2] + bc0[j];
                float v11 = d[i][j][3] + bc1[j];
                if (v1) {
                    *reinterpret_cast<__half2*>(out1 + 8 * j) = __floats2half2_rn(v00, v01);
                    aS0[j] += v00; aS1[j] += v01;
                    aQ0[j] += v00 * v00; aQ1[j] += v01 * v01;
                }
                if (v2) {
                    *reinterpret_cast<__half2*>(out2 + 8 * j) = __floats2half2_rn(v10, v11);
                    aS0[j] += v10; aS1[j] += v11;
                    aQ0[j] += v10 * v10; aQ1[j] += v11 * v11;
                }
            }
        }
    }

    // ----- one-shot BN1 stats reduction -----
#pragma unroll
    for (int j = 0; j < 4; ++j) {
#pragma unroll
        for (int ofs = 4; ofs <= 16; ofs <<= 1) {
            aS0[j] += __shfl_xor_sync(0xFFFFFFFF, aS0[j], ofs);
            aS1[j] += __shfl_xor_sync(0xFFFFFFFF, aS1[j], ofs);
            aQ0[j] += __shfl_xor_sync(0xFFFFFFFF, aQ0[j], ofs);
            aQ1[j] += __shfl_xor_sync(0xFFFFFFFF, aQ1[j], ofs);
        }
        if (lane < 4) {
            const int c = wn + 2 * lane + 8 * j;
            atomicAdd(&sstat[c], aS0[j]);
            atomicAdd(&sstat[c + 1], aS1[j]);
            atomicAdd(&sstat[COUT + c], aQ0[j]);
            atomicAdd(&sstat[COUT + c + 1], aQ1[j]);
        }
    }
    __syncthreads();
    atomicAdd(&g_stats1[tid], sstat[tid]);
}

__device__ __forceinline__ float softplus_fast(float x) {
    return fmaxf(x, 0.f) + __logf(1.f + __expf(-fabsf(x)));
}

// launch 4
__global__ __launch_bounds__(256) void msg_segsum_kernel(
    const int* __restrict__ selfIdx,
    const float* __restrict__ gamma1, const float* __restrict__ beta1,
    int E, float invE)
{
    __shared__ float s1[128], t1[128];
    const int tid = threadIdx.x;
    if (tid < 128) {
        float mean = g_stats1[tid] * invE;
        float var  = g_stats1[128 + tid] * invE - mean * mean;
        float r = rsqrtf(var + EPS);
        float g = gamma1[tid];
        s1[tid] = g * r;
        t1[tid] = beta1[tid] - g * mean * r;
    }
    __syncthreads();

    const int c = tid & 63;
    const int lane = tid >> 6;
    const int CHUNK = 64;
    long gl = (long)blockIdx.x * 4 + lane;
    int es = (int)(gl * CHUNK);
    if (es >= E) return;
    int ee = min(es + CHUNK, E);

    const float sf = s1[c],      tf = t1[c];
    const float sc = s1[64 + c], tc = t1[64 + c];

    int cur = selfIdx[es];
    float accv = 0.f;
    for (int e = es; e < ee; ++e) {
        int a = selfIdx[e];
        if (a != cur) {
            atomicAdd(&g_sums[(size_t)cur * ELEMF + c], accv);
            cur = a; accv = 0.f;
        }
        const __half* hp = g_hidden2 + (size_t)e * COUT;
        float f = fmaf(sf, __half2float(hp[c]), tf);
        float g = fmaf(sc, __half2float(hp[64 + c]), tc);
        float sig = __fdividef(1.f, 1.f + __expf(-f));
        accv = fmaf(sig, softplus_fast(g), accv);
    }
    atomicAdd(&g_sums[(size_t)cur * ELEMF + c], accv);
}

// launch 5
__global__ __launch_bounds__(256) void stats2_kernel(int Nn) {
    __shared__ float rs[4][64];
    __shared__ float rq[4][64];
    const int tid = threadIdx.x;
    const int c = tid & 63, rl = tid >> 6;
    float s = 0.f, q = 0.f;
    for (int row = blockIdx.x * 4 + rl; row < Nn; row += gridDim.x * 4) {
        float v = g_sums[(size_t)row * ELEMF + c];
        s += v; q += v * v;
    }
    rs[rl][c] = s; rq[rl][c] = q;
    __syncthreads();
    if (tid < 64) {
        float ss = 0.f, qq = 0.f;
#pragma unroll
        for (int r = 0; r < 4; ++r) { ss += rs[r][tid]; qq += rq[r][tid]; }
        atomicAdd(&g_stats2[tid], ss);
        atomicAdd(&g_stats2[64 + tid], qq);
    }
}

// launch 6
__device__ __forceinline__ float softplusf(float x) {
    return (x > 15.f) ? x : log1pf(expf(x));
}
__global__ __launch_bounds__(256) void out_kernel(
    const float* __restrict__ atom,
    const float* __restrict__ gamma2, const float* __restrict__ beta2,
    float* __restrict__ outp, int Nn, float invN)
{
    __shared__ float s2[64], t2[64];
    const int tid = threadIdx.x;
    if (tid < 64) {
        float mean = g_stats2[tid] * invN;
        float var  = g_stats2[64 + tid] * invN - mean * mean;
        float r = rsqrtf(var + EPS);
        float g = gamma2[tid];
        s2[tid] = g * r;
        t2[tid] = beta2[tid] - g * mean * r;
    }
    __syncthreads();
    const int c = tid & 63, rl = tid >> 6;
    for (int row = blockIdx.x * 4 + rl; row < Nn; row += gridDim.x * 4) {
        size_t idx = (size_t)row * ELEMF + c;
        float v = fmaf(s2[c], g_sums[idx], t2[c]) + atom[idx];
        outp[idx] = softplusf(v);
    }
}

extern "C" void kernel_launch(void* const* d_in, const int* in_sizes, int n_in,
                              void* d_out, int out_size)
{
    const float* atom   = (const float*)d_in[0];
    const float* nbrfea = (const float*)d_in[1];
    const int*   sIdx   = (const int*)d_in[2];
    const int*   nIdx   = (const int*)d_in[3];
    const float* W      = (const float*)d_in[4];
    const float* b      = (const float*)d_in[5];
    const float* gamma1 = (const float*)d_in[6];
    const float* beta1  = (const float*)d_in[7];
    const float* gamma2 = (const float*)d_in[8];
    const float* beta2  = (const float*)d_in[9];
    float* outp = (float*)d_out;

    const int Nn = in_sizes[0] / ELEMF;
    const int E  = in_sizes[2];
    const int nTiles = (E + 127) / 128;

    const int SMEM_BYTES = 2 * TILE_BYTES + 512 + 1024;   // 87552
    cudaFuncSetAttribute(gemm_tc_kernel,
                         cudaFuncAttributeMaxDynamicSharedMemorySize, SMEM_BYTES);
    int sms = 148;
    cudaDeviceGetAttribute(&sms, cudaDevAttrMultiProcessorCount, 0);
    int grid = 2 * sms < nTiles ? 2 * sms : nTiles;

    zero_kernel<<<2048, 256>>>(Nn * ELEMF);
    wconv_kernel<<<(128 * KTOT + 255) / 256, 256>>>(W);
    aconv_kernel<<<(Nn * ELEMF + 255) / 256, 256>>>(atom, Nn * ELEMF);
    gemm_tc_kernel<<<grid, 256, SMEM_BYTES>>>(nbrfea, sIdx, nIdx, b, E, nTiles);

    int lanes = (E + 63) / 64;
    int msg_blocks = (lanes + 3) / 4;
    msg_segsum_kernel<<<msg_blocks, 256>>>(sIdx, gamma1, beta1, E, 1.f / (float)E);

    stats2_kernel<<<592, 256>>>(Nn);

    int out_blocks = (Nn + 3) / 4;
    out_kernel<<<out_blocks, 256>>>(atom, gamma2, beta2, outp, Nn, 1.f / (float)Nn);
}

// round 7
// speedup vs baseline: 2.2949x; 1.0280x over previous
#include <cuda_runtime.h>
#include <cuda_fp16.h>

#define ELEMF 64
#define NBRF  32
#define COUT  128
#define KTOT  160
#define EPS   1e-5f
#define E_MAX 1600000
#define N_MAX 50000

// fp16 smem rows: 168 halves = 336 bytes (84 banks -> conflict-free LDSM)
#define RSTRIDE_B 336
#define ATILE_BYTES (256 * RSTRIDE_B)   // 86016 (M=256 tile)
#define BTILE_BYTES (128 * RSTRIDE_B)   // 43008

// ---------------- scratch (device globals; no allocation allowed) -----------
__device__ __half g_hidden2[(size_t)E_MAX * COUT]; // pre-BN1 hidden (E,128) fp16
__device__ float g_sums[(size_t)N_MAX * ELEMF];    // segment sums (N,64)
__device__ float g_stats1[2 * COUT];
__device__ float g_stats2[2 * ELEMF];
__device__ unsigned char g_Wf[BTILE_BYTES];        // W fp16 [n][k], rows of 336B
__device__ __half g_atomF[(size_t)N_MAX * ELEMF];  // atom table fp16
__device__ __half g_edgeF[(size_t)E_MAX * NBRF];   // edge features fp16

// ---------------- helpers -----------------------------------------------------
__device__ __forceinline__ unsigned smem_u32(const void* p) {
    unsigned a;
    asm("{ .reg .u64 t; cvta.to.shared.u64 t, %1; cvt.u32.u64 %0, t; }"
        : "=r"(a) : "l"(p));
    return a;
}
__device__ __forceinline__ void ldsm4(unsigned addr, unsigned& r0, unsigned& r1,
                                      unsigned& r2, unsigned& r3) {
    asm volatile("ldmatrix.sync.aligned.m8n8.x4.shared.b16 {%0,%1,%2,%3}, [%4];"
                 : "=r"(r0), "=r"(r1), "=r"(r2), "=r"(r3) : "r"(addr));
}
__device__ __forceinline__ void mma16816(float* d, const unsigned* a,
                                         unsigned b0, unsigned b1) {
    asm volatile("mma.sync.aligned.m16n8k16.row.col.f32.f16.f16.f32 "
                 "{%0,%1,%2,%3}, {%4,%5,%6,%7}, {%8,%9}, {%0,%1,%2,%3};"
                 : "+f"(d[0]), "+f"(d[1]), "+f"(d[2]), "+f"(d[3])
                 : "r"(a[0]), "r"(a[1]), "r"(a[2]), "r"(a[3]), "r"(b0), "r"(b1));
}
__device__ __forceinline__ void cp16ca(unsigned dst, const void* src) {
    asm volatile("cp.async.ca.shared.global [%0], [%1], 16;"
                 :: "r"(dst), "l"(src) : "memory");
}
__device__ __forceinline__ void cp16cg(unsigned dst, const void* src) {
    asm volatile("cp.async.cg.shared.global [%0], [%1], 16;"
                 :: "r"(dst), "l"(src) : "memory");
}
#define CP_COMMIT() asm volatile("cp.async.commit_group;" ::: "memory")
#define CP_WAIT(n)  asm volatile("cp.async.wait_group %0;" :: "n"(n) : "memory")

// ---------------- kernels ----------------------------------------------------
// launch 0
__global__ void zero_kernel(int n_sums) {
    int i = blockIdx.x * blockDim.x + threadIdx.x;
    int stride = gridDim.x * blockDim.x;
    for (int j = i; j < n_sums; j += stride) g_sums[j] = 0.f;
    if (i < 2 * COUT)  g_stats1[i] = 0.f;
    if (i < 2 * ELEMF) g_stats2[i] = 0.f;
}

// launch 1: W (160x128 fp32 [k][n]) -> fp16 [n][k] rows of 336B
__global__ void wconv_kernel(const float* __restrict__ W) {
    int i = blockIdx.x * blockDim.x + threadIdx.x;
    if (i >= 128 * KTOT) return;
    int k = i % KTOT;
    int n = i / KTOT;
    *reinterpret_cast<__half*>(g_Wf + n * RSTRIDE_B + k * 2) =
        __float2half_rn(W[k * COUT + n]);
}

// launch 2: atom + edge tables fp32 -> fp16 (one kernel so GEMM stays index 3)
__global__ void prep_kernel(const float* __restrict__ atom,
                            const float* __restrict__ nbrfea,
                            int nAtom, int nEdge) {
    int i = blockIdx.x * blockDim.x + threadIdx.x;
    if (i < nAtom) g_atomF[i] = __float2half_rn(atom[i]);
    int j = i - nAtom;
    if (j >= 0 && j < nEdge) g_edgeF[j] = __float2half_rn(nbrfea[j]);
}

// launch 3 (ncu captures this): persistent fp16 HMMA gather-GEMM.
// M=256 tile, 512 threads (4m x 4n warps, warp tile m64 x n32),
// double-buffered A via cp.async.
__global__ __launch_bounds__(512, 1) void gemm_tc_kernel(
    const int* __restrict__ selfIdx, const int* __restrict__ nbrIdx,
    const float* __restrict__ bias, int E, int nTiles)
{
    extern __shared__ char smem[];
    const unsigned sbase = smem_u32(smem);

    const int A0_OFF   = 0;
    const int B_OFF    = 2 * ATILE_BYTES;          // 172032
    const int BIAS_OFF = 2 * ATILE_BYTES + BTILE_BYTES;   // 215040
    const int STAT_OFF = BIAS_OFF + 512;           // 215552

    const int tid = threadIdx.x, wid = tid >> 5, lane = tid & 31;

    // B tile + bias -> smem once
    {
        const uint4* src = reinterpret_cast<const uint4*>(g_Wf);
        uint4* dst = reinterpret_cast<uint4*>(smem + B_OFF);
        for (int i = tid; i < BTILE_BYTES / 16; i += 512) dst[i] = src[i];
    }
    if (tid < COUT) reinterpret_cast<float*>(smem + BIAS_OFF)[tid] = bias[tid];
    if (tid < 256)  reinterpret_cast<float*>(smem + STAT_OFF)[tid] = 0.f;
    __syncthreads();

    const int wm = (wid >> 2) * 64;              // 4 m-warps
    const int wn = (wid & 3) * 32;               // 4 n-warps
    const unsigned lane_off = (lane & 15) * RSTRIDE_B + ((lane >> 4) << 4);

    const int cb = wn + 2 * (lane & 3);
    float bc0[4], bc1[4];
#pragma unroll
    for (int j = 0; j < 4; ++j) {
        bc0[j] = reinterpret_cast<float*>(smem + BIAS_OFF)[cb + 8 * j];
        bc1[j] = reinterpret_cast<float*>(smem + BIAS_OFF)[cb + 8 * j + 1];
    }
    const unsigned bbase = sbase + B_OFF + wn * RSTRIDE_B + lane_off;
    float* sstat = reinterpret_cast<float*>(smem + STAT_OFF);

    // gather mapping: thread = (row r, half h)
    const int gr = tid >> 1, gh = tid & 1;

    // cross-tile BN1 stats in registers
    float aS0[4] = {0,0,0,0}, aS1[4] = {0,0,0,0};
    float aQ0[4] = {0,0,0,0}, aQ1[4] = {0,0,0,0};

    // ---- prologue: issue gather for first tile into buf 0 ----
    int tile = blockIdx.x;
    if (tile < nTiles) {
        const int e = tile * 256 + gr;
        if (e < E) {
            const int si = selfIdx[e], ni = nbrIdx[e];
            const unsigned rowA = sbase + A0_OFF + gr * RSTRIDE_B;
            const char* sp = reinterpret_cast<const char*>(g_atomF + (size_t)si * ELEMF) + gh * 64;
            const char* np = reinterpret_cast<const char*>(g_atomF + (size_t)ni * ELEMF) + gh * 64;
#pragma unroll
            for (int g = 0; g < 4; ++g) {
                cp16ca(rowA + gh * 64 + g * 16, sp + g * 16);
                cp16ca(rowA + 128 + gh * 64 + g * 16, np + g * 16);
            }
            const char* ep = reinterpret_cast<const char*>(g_edgeF + (size_t)e * NBRF) + gh * 32;
            cp16cg(rowA + 256 + gh * 32, ep);
            cp16cg(rowA + 256 + gh * 32 + 16, ep + 16);
        }
    }
    CP_COMMIT();

    int buf = 0;
    for (; tile < nTiles; tile += gridDim.x) {
        const int eb = tile * 256;
        const int next = tile + gridDim.x;

        // ---- issue gather for next tile into buf^1, then wait for current ----
        if (next < nTiles) {
            const int e = next * 256 + gr;
            if (e < E) {
                const int si = selfIdx[e], ni = nbrIdx[e];
                const unsigned rowA = sbase + (buf ^ 1) * ATILE_BYTES + gr * RSTRIDE_B;
                const char* sp = reinterpret_cast<const char*>(g_atomF + (size_t)si * ELEMF) + gh * 64;
                const char* np = reinterpret_cast<const char*>(g_atomF + (size_t)ni * ELEMF) + gh * 64;
#pragma unroll
                for (int g = 0; g < 4; ++g) {
                    cp16ca(rowA + gh * 64 + g * 16, sp + g * 16);
                    cp16ca(rowA + 128 + gh * 64 + g * 16, np + g * 16);
                }
                const char* ep = reinterpret_cast<const char*>(g_edgeF + (size_t)e * NBRF) + gh * 32;
                cp16cg(rowA + 256 + gh * 32, ep);
                cp16cg(rowA + 256 + gh * 32 + 16, ep + 16);
            }
            CP_COMMIT();
            CP_WAIT(1);
        } else {
            CP_WAIT(0);
        }
        __syncthreads();

        // ---- mainloop on buf ----
        const unsigned abase = sbase + buf * ATILE_BYTES + wm * RSTRIDE_B + lane_off;
        float d[4][4][4];
#pragma unroll
        for (int i = 0; i < 4; ++i)
#pragma unroll
            for (int j = 0; j < 4; ++j)
#pragma unroll
                for (int q2 = 0; q2 < 4; ++q2) d[i][j][q2] = 0.f;

#pragma unroll
        for (int kk = 0; kk < 10; ++kk) {
            const unsigned kb = kk * 32;
            unsigned a[4][4];
#pragma unroll
            for (int i = 0; i < 4; ++i)
                ldsm4(abase + i * 16 * RSTRIDE_B + kb,
                      a[i][0], a[i][1], a[i][2], a[i][3]);
            unsigned u0, u1, u2, u3, w0, w1, w2, w3;
            ldsm4(bbase + kb,                  u0, u1, u2, u3);
            ldsm4(bbase + 16 * RSTRIDE_B + kb, w0, w1, w2, w3);
#pragma unroll
            for (int i = 0; i < 4; ++i) {
                mma16816(d[i][0], a[i], u0, u2);
                mma16816(d[i][1], a[i], u1, u3);
                mma16816(d[i][2], a[i], w0, w2);
                mma16816(d[i][3], a[i], w1, w3);
            }
        }
        __syncthreads();   // all LDSM on buf done before next iter's cp.async reuses it

        // ---- epilogue: bias, fp16 store, register stats ----
#pragma unroll
        for (int i = 0; i < 4; ++i) {
            const int e1 = eb + wm + 16 * i + (lane >> 2);
            const int e2 = e1 + 8;
            const bool v1 = (e1 < E), v2 = (e2 < E);
            __half* out1 = g_hidden2 + (size_t)e1 * COUT + cb;
            __half* out2 = g_hidden2 + (size_t)e2 * COUT + cb;
#pragma unroll
            for (int j = 0; j < 4; ++j) {
                float v00 = d[i][j][0] + bc0[j];
                float v01 = d[i][j][1] + bc1[j];
                float v10 = d[i][j][2] + bc0[j];
                float v11 = d[i][j][3] + bc1[j];
                if (v1) {
                    *reinterpret_cast<__half2*>(out1 + 8 * j) = __floats2half2_rn(v00, v01);
                    aS0[j] += v00; aS1[j] += v01;
                    aQ0[j] += v00 * v00; aQ1[j] += v01 * v01;
                }
                if (v2) {
                    *reinterpret_cast<__half2*>(out2 + 8 * j) = __floats2half2_rn(v10, v11);
                    aS0[j] += v10; aS1[j] += v11;
                    aQ0[j] += v10 * v10; aQ1[j] += v11 * v11;
                }
            }
        }
        buf ^= 1;
    }

    // ---- one-shot BN1 stats reduction ----
#pragma unroll
    for (int j = 0; j < 4; ++j) {
#pragma unroll
        for (int ofs = 4; ofs <= 16; ofs <<= 1) {
            aS0[j] += __shfl_xor_sync(0xFFFFFFFF, aS0[j], ofs);
            aS1[j] += __shfl_xor_sync(0xFFFFFFFF, aS1[j], ofs);
            aQ0[j] += __shfl_xor_sync(0xFFFFFFFF, aQ0[j], ofs);
            aQ1[j] += __shfl_xor_sync(0xFFFFFFFF, aQ1[j], ofs);
        }
        if (lane < 4) {
            const int c = wn + 2 * lane + 8 * j;
            atomicAdd(&sstat[c], aS0[j]);
            atomicAdd(&sstat[c + 1], aS1[j]);
            atomicAdd(&sstat[COUT + c], aQ0[j]);
            atomicAdd(&sstat[COUT + c + 1], aQ1[j]);
        }
    }
    __syncthreads();
    if (tid < 256) atomicAdd(&g_stats1[tid], sstat[tid]);
}

__device__ __forceinline__ float softplus_fast(float x) {
    return fmaxf(x, 0.f) + __logf(1.f + __expf(-fabsf(x)));
}

// launch 4
__global__ __launch_bounds__(256) void msg_segsum_kernel(
    const int* __restrict__ selfIdx,
    const float* __restrict__ gamma1, const float* __restrict__ beta1,
    int E, float invE)
{
    __shared__ float s1[128], t1[128];
    const int tid = threadIdx.x;
    if (tid < 128) {
        float mean = g_stats1[tid] * invE;
        float var  = g_stats1[128 + tid] * invE - mean * mean;
        float r = rsqrtf(var + EPS);
        float g = gamma1[tid];
        s1[tid] = g * r;
        t1[tid] = beta1[tid] - g * mean * r;
    }
    __syncthreads();

    const int c = tid & 63;
    const int lane = tid >> 6;
    const int CHUNK = 64;
    long gl = (long)blockIdx.x * 4 + lane;
    int es = (int)(gl * CHUNK);
    if (es >= E) return;
    int ee = min(es + CHUNK, E);

    const float sf = s1[c],      tf = t1[c];
    const float sc = s1[64 + c], tc = t1[64 + c];

    int cur = selfIdx[es];
    float accv = 0.f;
    for (int e = es; e < ee; ++e) {
        int a = selfIdx[e];
        if (a != cur) {
            atomicAdd(&g_sums[(size_t)cur * ELEMF + c], accv);
            cur = a; accv = 0.f;
        }
        const __half* hp = g_hidden2 + (size_t)e * COUT;
        float f = fmaf(sf, __half2float(hp[c]), tf);
        float g = fmaf(sc, __half2float(hp[64 + c]), tc);
        float sig = __fdividef(1.f, 1.f + __expf(-f));
        accv = fmaf(sig, softplus_fast(g), accv);
    }
    atomicAdd(&g_sums[(size_t)cur * ELEMF + c], accv);
}

// launch 5
__global__ __launch_bounds__(256) void stats2_kernel(int Nn) {
    __shared__ float rs[4][64];
    __shared__ float rq[4][64];
    const int tid = threadIdx.x;
    const int c = tid & 63, rl = tid >> 6;
    float s = 0.f, q = 0.f;
    for (int row = blockIdx.x * 4 + rl; row < Nn; row += gridDim.x * 4) {
        float v = g_sums[(size_t)row * ELEMF + c];
        s += v; q += v * v;
    }
    rs[rl][c] = s; rq[rl][c] = q;
    __syncthreads();
    if (tid < 64) {
        float ss = 0.f, qq = 0.f;
#pragma unroll
        for (int r = 0; r < 4; ++r) { ss += rs[r][tid]; qq += rq[r][tid]; }
        atomicAdd(&g_stats2[tid], ss);
        atomicAdd(&g_stats2[64 + tid], qq);
    }
}

// launch 6
__device__ __forceinline__ float softplusf(float x) {
    return (x > 15.f) ? x : log1pf(expf(x));
}
__global__ __launch_bounds__(256) void out_kernel(
    const float* __restrict__ atom,
    const float* __restrict__ gamma2, const float* __restrict__ beta2,
    float* __restrict__ outp, int Nn, float invN)
{
    __shared__ float s2[64], t2[64];
    const int tid = threadIdx.x;
    if (tid < 64) {
        float mean = g_stats2[tid] * invN;
        float var  = g_stats2[64 + tid] * invN - mean * mean;
        float r = rsqrtf(var + EPS);
        float g = gamma2[tid];
        s2[tid] = g * r;
        t2[tid] = beta2[tid] - g * mean * r;
    }
    __syncthreads();
    const int c = tid & 63, rl = tid >> 6;
    for (int row = blockIdx.x * 4 + rl; row < Nn; row += gridDim.x * 4) {
        size_t idx = (size_t)row * ELEMF + c;
        float v = fmaf(s2[c], g_sums[idx], t2[c]) + atom[idx];
        outp[idx] = softplusf(v);
    }
}

extern "C" void kernel_launch(void* const* d_in, const int* in_sizes, int n_in,
                              void* d_out, int out_size)
{
    const float* atom   = (const float*)d_in[0];
    const float* nbrfea = (const float*)d_in[1];
    const int*   sIdx   = (const int*)d_in[2];
    const int*   nIdx   = (const int*)d_in[3];
    const float* W      = (const float*)d_in[4];
    const float* b      = (const float*)d_in[5];
    const float* gamma1 = (const float*)d_in[6];
    const float* beta1  = (const float*)d_in[7];
    const float* gamma2 = (const float*)d_in[8];
    const float* beta2  = (const float*)d_in[9];
    float* outp = (float*)d_out;

    const int Nn = in_sizes[0] / ELEMF;
    const int E  = in_sizes[2];
    const int nTiles = (E + 255) / 256;

    const int SMEM_BYTES = 2 * ATILE_BYTES + BTILE_BYTES + 512 + 1024;  // 216576
    cudaFuncSetAttribute(gemm_tc_kernel,
                         cudaFuncAttributeMaxDynamicSharedMemorySize, SMEM_BYTES);
    int sms = 148;
    cudaDeviceGetAttribute(&sms, cudaDevAttrMultiProcessorCount, 0);
    int grid = sms < nTiles ? sms : nTiles;

    const int nAtom = Nn * ELEMF, nEdge = E * NBRF;

    zero_kernel<<<2048, 256>>>(nAtom);
    wconv_kernel<<<(128 * KTOT + 255) / 256, 256>>>(W);
    prep_kernel<<<(nAtom + nEdge + 255) / 256, 256>>>(atom, nbrfea, nAtom, nEdge);
    gemm_tc_kernel<<<grid, 512, SMEM_BYTES>>>(sIdx, nIdx, b, E, nTiles);

    int lanes = (E + 63) / 64;
    int msg_blocks = (lanes + 3) / 4;
    msg_segsum_kernel<<<msg_blocks, 256>>>(sIdx, gamma1, beta1, E, 1.f / (float)E);

    stats2_kernel<<<592, 256>>>(Nn);

    int out_blocks = (Nn + 3) / 4;
    out_kernel<<<out_blocks, 256>>>(atom, gamma2, beta2, outp, Nn, 1.f / (float)Nn);
}

// round 8
// speedup vs baseline: 2.5866x; 1.1271x over previous
#include <cuda_runtime.h>
#include <cuda_fp16.h>

#define ELEMF 64
#define NBRF  32
#define COUT  128
#define KTOT  160
#define EPS   1e-5f
#define E_MAX 1600000
#define N_MAX 50000

// fp16 smem rows: 168 halves = 336 bytes (84 banks -> conflict-free LDSM)
#define RSTRIDE_B 336
#define ATILE_BYTES (256 * RSTRIDE_B)   // 86016 (M=256 tile)
#define BTILE_BYTES (128 * RSTRIDE_B)   // 43008

// ---------------- scratch (device globals; no allocation allowed) -----------
__device__ __half g_hidden2[(size_t)E_MAX * COUT]; // pre-BN1 hidden (E,128) fp16
__device__ float g_sums[(size_t)N_MAX * ELEMF];    // segment sums (N,64)
__device__ float g_stats1[2 * COUT];
__device__ float g_stats2[2 * ELEMF];
__device__ unsigned char g_Wf[BTILE_BYTES];        // W fp16 [n][k], rows of 336B
__device__ __half g_atomF[(size_t)N_MAX * ELEMF];  // atom table fp16
__device__ __half g_edgeF[(size_t)E_MAX * NBRF];   // edge features fp16

// ---------------- helpers -----------------------------------------------------
__device__ __forceinline__ unsigned smem_u32(const void* p) {
    unsigned a;
    asm("{ .reg .u64 t; cvta.to.shared.u64 t, %1; cvt.u32.u64 %0, t; }"
        : "=r"(a) : "l"(p));
    return a;
}
__device__ __forceinline__ void ldsm4(unsigned addr, unsigned& r0, unsigned& r1,
                                      unsigned& r2, unsigned& r3) {
    asm volatile("ldmatrix.sync.aligned.m8n8.x4.shared.b16 {%0,%1,%2,%3}, [%4];"
                 : "=r"(r0), "=r"(r1), "=r"(r2), "=r"(r3) : "r"(addr));
}
__device__ __forceinline__ void mma16816(float* d, const unsigned* a,
                                         unsigned b0, unsigned b1) {
    asm volatile("mma.sync.aligned.m16n8k16.row.col.f32.f16.f16.f32 "
                 "{%0,%1,%2,%3}, {%4,%5,%6,%7}, {%8,%9}, {%0,%1,%2,%3};"
                 : "+f"(d[0]), "+f"(d[1]), "+f"(d[2]), "+f"(d[3])
                 : "r"(a[0]), "r"(a[1]), "r"(a[2]), "r"(a[3]), "r"(b0), "r"(b1));
}
__device__ __forceinline__ void cp16ca(unsigned dst, const void* src) {
    asm volatile("cp.async.ca.shared.global [%0], [%1], 16;"
                 :: "r"(dst), "l"(src) : "memory");
}
__device__ __forceinline__ void cp16cg(unsigned dst, const void* src) {
    asm volatile("cp.async.cg.shared.global [%0], [%1], 16;"
                 :: "r"(dst), "l"(src) : "memory");
}
#define CP_COMMIT() asm volatile("cp.async.commit_group;" ::: "memory")
#define CP_WAIT(n)  asm volatile("cp.async.wait_group %0;" :: "n"(n) : "memory")

// ---------------- kernels ----------------------------------------------------
// launch 0
__global__ void zero_kernel(int n_sums) {
    int i = blockIdx.x * blockDim.x + threadIdx.x;
    int stride = gridDim.x * blockDim.x;
    for (int j = i; j < n_sums; j += stride) g_sums[j] = 0.f;
    if (i < 2 * COUT)  g_stats1[i] = 0.f;
    if (i < 2 * ELEMF) g_stats2[i] = 0.f;
}

// launch 1: W (160x128 fp32 [k][n]) -> fp16 [n][k] rows of 336B
__global__ void wconv_kernel(const float* __restrict__ W) {
    int i = blockIdx.x * blockDim.x + threadIdx.x;
    if (i >= 128 * KTOT) return;
    int k = i % KTOT;
    int n = i / KTOT;
    *reinterpret_cast<__half*>(g_Wf + n * RSTRIDE_B + k * 2) =
        __float2half_rn(W[k * COUT + n]);
}

// launch 2: atom + edge tables fp32 -> fp16
__global__ void prep_kernel(const float* __restrict__ atom,
                            const float* __restrict__ nbrfea,
                            int nAtom, int nEdge) {
    int i = blockIdx.x * blockDim.x + threadIdx.x;
    if (i < nAtom) g_atomF[i] = __float2half_rn(atom[i]);
    int j = i - nAtom;
    if (j >= 0 && j < nEdge) g_edgeF[j] = __float2half_rn(nbrfea[j]);
}

// launch 3 (ncu target): persistent fp16 HMMA gather-GEMM.
// M=256 tile, 512 threads (4m x 4n warps, warp tile m64 x n32),
// double-buffered A via cp.async; epilogue overlapped before the recycle barrier.
__global__ __launch_bounds__(512, 1) void gemm_tc_kernel(
    const int* __restrict__ selfIdx, const int* __restrict__ nbrIdx,
    const float* __restrict__ bias, int E, int nTiles)
{
    extern __shared__ char smem[];
    const unsigned sbase = smem_u32(smem);

    const int A0_OFF   = 0;
    const int B_OFF    = 2 * ATILE_BYTES;                 // 172032
    const int BIAS_OFF = 2 * ATILE_BYTES + BTILE_BYTES;   // 215040
    const int STAT_OFF = BIAS_OFF + 512;                  // 215552

    const int tid = threadIdx.x, wid = tid >> 5, lane = tid & 31;

    {
        const uint4* src = reinterpret_cast<const uint4*>(g_Wf);
        uint4* dst = reinterpret_cast<uint4*>(smem + B_OFF);
        for (int i = tid; i < BTILE_BYTES / 16; i += 512) dst[i] = src[i];
    }
    if (tid < COUT) reinterpret_cast<float*>(smem + BIAS_OFF)[tid] = bias[tid];
    if (tid < 256)  reinterpret_cast<float*>(smem + STAT_OFF)[tid] = 0.f;
    __syncthreads();

    const int wm = (wid >> 2) * 64;
    const int wn = (wid & 3) * 32;
    const unsigned lane_off = (lane & 15) * RSTRIDE_B + ((lane >> 4) << 4);

    const int cb = wn + 2 * (lane & 3);
    float bc0[4], bc1[4];
#pragma unroll
    for (int j = 0; j < 4; ++j) {
        bc0[j] = reinterpret_cast<float*>(smem + BIAS_OFF)[cb + 8 * j];
        bc1[j] = reinterpret_cast<float*>(smem + BIAS_OFF)[cb + 8 * j + 1];
    }
    const unsigned bbase = sbase + B_OFF + wn * RSTRIDE_B + lane_off;
    float* sstat = reinterpret_cast<float*>(smem + STAT_OFF);

    const int gr = tid >> 1, gh = tid & 1;

    float aS0[4] = {0,0,0,0}, aS1[4] = {0,0,0,0};
    float aQ0[4] = {0,0,0,0}, aQ1[4] = {0,0,0,0};

    // prologue: gather first tile into buf 0
    int tile = blockIdx.x;
    if (tile < nTiles) {
        const int e = tile * 256 + gr;
        if (e < E) {
            const int si = selfIdx[e], ni = nbrIdx[e];
            const unsigned rowA = sbase + A0_OFF + gr * RSTRIDE_B;
            const char* sp = reinterpret_cast<const char*>(g_atomF + (size_t)si * ELEMF) + gh * 64;
            const char* np = reinterpret_cast<const char*>(g_atomF + (size_t)ni * ELEMF) + gh * 64;
#pragma unroll
            for (int g = 0; g < 4; ++g) {
                cp16ca(rowA + gh * 64 + g * 16, sp + g * 16);
                cp16ca(rowA + 128 + gh * 64 + g * 16, np + g * 16);
            }
            const char* ep = reinterpret_cast<const char*>(g_edgeF + (size_t)e * NBRF) + gh * 32;
            cp16cg(rowA + 256 + gh * 32, ep);
            cp16cg(rowA + 256 + gh * 32 + 16, ep + 16);
        }
    }
    CP_COMMIT();

    int buf = 0;
    for (; tile < nTiles; tile += gridDim.x) {
        const int eb = tile * 256;
        const int next = tile + gridDim.x;

        if (next < nTiles) {
            const int e = next * 256 + gr;
            if (e < E) {
                const int si = selfIdx[e], ni = nbrIdx[e];
                const unsigned rowA = sbase + (buf ^ 1) * ATILE_BYTES + gr * RSTRIDE_B;
                const char* sp = reinterpret_cast<const char*>(g_atomF + (size_t)si * ELEMF) + gh * 64;
                const char* np = reinterpret_cast<const char*>(g_atomF + (size_t)ni * ELEMF) + gh * 64;
#pragma unroll
                for (int g = 0; g < 4; ++g) {
                    cp16ca(rowA + gh * 64 + g * 16, sp + g * 16);
                    cp16ca(rowA + 128 + gh * 64 + g * 16, np + g * 16);
                }
                const char* ep = reinterpret_cast<const char*>(g_edgeF + (size_t)e * NBRF) + gh * 32;
                cp16cg(rowA + 256 + gh * 32, ep);
                cp16cg(rowA + 256 + gh * 32 + 16, ep + 16);
            }
            CP_COMMIT();
            CP_WAIT(1);
        } else {
            CP_WAIT(0);
        }
        __syncthreads();   // current buf visible to all warps

        const unsigned abase = sbase + buf * ATILE_BYTES + wm * RSTRIDE_B + lane_off;
        float d[4][4][4];
#pragma unroll
        for (int i = 0; i < 4; ++i)
#pragma unroll
            for (int j = 0; j < 4; ++j)
#pragma unroll
                for (int q2 = 0; q2 < 4; ++q2) d[i][j][q2] = 0.f;

#pragma unroll
        for (int kk = 0; kk < 10; ++kk) {
            const unsigned kb = kk * 32;
            unsigned a[4][4];
#pragma unroll
            for (int i = 0; i < 4; ++i)
                ldsm4(abase + i * 16 * RSTRIDE_B + kb,
                      a[i][0], a[i][1], a[i][2], a[i][3]);
            unsigned u0, u1, u2, u3, w0, w1, w2, w3;
            ldsm4(bbase + kb,                  u0, u1, u2, u3);
            ldsm4(bbase + 16 * RSTRIDE_B + kb, w0, w1, w2, w3);
#pragma unroll
            for (int i = 0; i < 4; ++i) {
                mma16816(d[i][0], a[i], u0, u2);
                mma16816(d[i][1], a[i], u1, u3);
                mma16816(d[i][2], a[i], w0, w2);
                mma16816(d[i][3], a[i], w1, w3);
            }
        }

        // epilogue BEFORE the recycle barrier: overlaps with other warps' mainloop tails
#pragma unroll
        for (int i = 0; i < 4; ++i) {
            const int e1 = eb + wm + 16 * i + (lane >> 2);
            const int e2 = e1 + 8;
            const bool v1 = (e1 < E), v2 = (e2 < E);
            __half* out1 = g_hidden2 + (size_t)e1 * COUT + cb;
            __half* out2 = g_hidden2 + (size_t)e2 * COUT + cb;
#pragma unroll
            for (int j = 0; j < 4; ++j) {
                float v00 = d[i][j][0] + bc0[j];
                float v01 = d[i][j][1] + bc1[j];
                float v10 = d[i][j][2] + bc0[j];
                float v11 = d[i][j][3] + bc1[j];
                if (v1) {
                    *reinterpret_cast<__half2*>(out1 + 8 * j) = __floats2half2_rn(v00, v01);
                    aS0[j] += v00; aS1[j] += v01;
                    aQ0[j] += v00 * v00; aQ1[j] += v01 * v01;
                }
                if (v2) {
                    *reinterpret_cast<__half2*>(out2 + 8 * j) = __floats2half2_rn(v10, v11);
                    aS0[j] += v10; aS1[j] += v11;
                    aQ0[j] += v10 * v10; aQ1[j] += v11 * v11;
                }
            }
        }
        __syncthreads();   // all LDSM on buf done before next iter's cp.async recycles it
        buf ^= 1;
    }

#pragma unroll
    for (int j = 0; j < 4; ++j) {
#pragma unroll
        for (int ofs = 4; ofs <= 16; ofs <<= 1) {
            aS0[j] += __shfl_xor_sync(0xFFFFFFFF, aS0[j], ofs);
            aS1[j] += __shfl_xor_sync(0xFFFFFFFF, aS1[j], ofs);
            aQ0[j] += __shfl_xor_sync(0xFFFFFFFF, aQ0[j], ofs);
            aQ1[j] += __shfl_xor_sync(0xFFFFFFFF, aQ1[j], ofs);
        }
        if (lane < 4) {
            const int c = wn + 2 * lane + 8 * j;
            atomicAdd(&sstat[c], aS0[j]);
            atomicAdd(&sstat[c + 1], aS1[j]);
            atomicAdd(&sstat[COUT + c], aQ0[j]);
            atomicAdd(&sstat[COUT + c + 1], aQ1[j]);
        }
    }
    __syncthreads();
    if (tid < 256) atomicAdd(&g_stats1[tid], sstat[tid]);
}

// launch 4: BN1 apply + gate + segment-sum, f16x2 math, fp32 accumulation.
// Thread = column-pair p (0..31) x chunk (tid>>5); warp shares the edge stream.
__global__ __launch_bounds__(256) void msg_segsum_kernel(
    const int* __restrict__ selfIdx,
    const float* __restrict__ gamma1, const float* __restrict__ beta1,
    int E, float invE)
{
    __shared__ float s1[128], t1[128];
    const int tid = threadIdx.x;
    if (tid < 128) {
        float mean = g_stats1[tid] * invE;
        float var  = g_stats1[128 + tid] * invE - mean * mean;
        float r = rsqrtf(var + EPS);
        float g = gamma1[tid];
        s1[tid] = g * r;
        t1[tid] = beta1[tid] - g * mean * r;
    }
    __syncthreads();

    const int p = tid & 31;          // column pair: cols (2p, 2p+1)
    const int chunk = tid >> 5;      // 8 chunks per block
    const int CHUNK = 64;
    long gl = (long)blockIdx.x * 8 + chunk;
    int es = (int)(gl * CHUNK);
    if (es >= E) return;
    int ee = min(es + CHUNK, E);

    const __half2 sf2 = __floats2half2_rn(s1[2*p],      s1[2*p + 1]);
    const __half2 tf2 = __floats2half2_rn(t1[2*p],      t1[2*p + 1]);
    const __half2 sc2 = __floats2half2_rn(s1[64 + 2*p], s1[64 + 2*p + 1]);
    const __half2 tc2 = __floats2half2_rn(t1[64 + 2*p], t1[64 + 2*p + 1]);
    const __half2 one2  = __floats2half2_rn(1.f, 1.f);
    const __half2 zero2 = __floats2half2_rn(0.f, 0.f);

    int cur = selfIdx[es];
    float acc0 = 0.f, acc1 = 0.f;
    for (int e = es; e < ee; ++e) {
        int a = selfIdx[e];                       // warp-uniform
        if (a != cur) {
            atomicAdd(&g_sums[(size_t)cur * ELEMF + 2*p],     acc0);
            atomicAdd(&g_sums[(size_t)cur * ELEMF + 2*p + 1], acc1);
            cur = a; acc0 = 0.f; acc1 = 0.f;
        }
        const __half2* hp = reinterpret_cast<const __half2*>(g_hidden2 + (size_t)e * COUT);
        __half2 f = __hfma2(sf2, hp[p], tf2);
        __half2 g = __hfma2(sc2, hp[32 + p], tc2);
        __half2 sig = h2rcp(__hadd2(one2, h2exp(__hneg2(f))));
        __half2 sp  = __hadd2(__hmax2(g, zero2),
                              h2log(__hadd2(one2, h2exp(__hneg2(__habs2(g))))));
        float2 m = __half22float2(__hmul2(sig, sp));
        acc0 += m.x; acc1 += m.y;
    }
    atomicAdd(&g_sums[(size_t)cur * ELEMF + 2*p],     acc0);
    atomicAdd(&g_sums[(size_t)cur * ELEMF + 2*p + 1], acc1);
}

// launch 5
__global__ __launch_bounds__(256) void stats2_kernel(int Nn) {
    __shared__ float rs[4][64];
    __shared__ float rq[4][64];
    const int tid = threadIdx.x;
    const int c = tid & 63, rl = tid >> 6;
    float s = 0.f, q = 0.f;
    for (int row = blockIdx.x * 4 + rl; row < Nn; row += gridDim.x * 4) {
        float v = g_sums[(size_t)row * ELEMF + c];
        s += v; q += v * v;
    }
    rs[rl][c] = s; rq[rl][c] = q;
    __syncthreads();
    if (tid < 64) {
        float ss = 0.f, qq = 0.f;
#pragma unroll
        for (int r = 0; r < 4; ++r) { ss += rs[r][tid]; qq += rq[r][tid]; }
        atomicAdd(&g_stats2[tid], ss);
        atomicAdd(&g_stats2[64 + tid], qq);
    }
}

// launch 6 (full precision for the final output)
__device__ __forceinline__ float softplusf(float x) {
    return (x > 15.f) ? x : log1pf(expf(x));
}
__global__ __launch_bounds__(256) void out_kernel(
    const float* __restrict__ atom,
    const float* __restrict__ gamma2, const float* __restrict__ beta2,
    float* __restrict__ outp, int Nn, float invN)
{
    __shared__ float s2[64], t2[64];
    const int tid = threadIdx.x;
    if (tid < 64) {
        float mean = g_stats2[tid] * invN;
        float var  = g_stats2[64 + tid] * invN - mean * mean;
        float r = rsqrtf(var + EPS);
        float g = gamma2[tid];
        s2[tid] = g * r;
        t2[tid] = beta2[tid] - g * mean * r;
    }
    __syncthreads();
    const int c = tid & 63, rl = tid >> 6;
    for (int row = blockIdx.x * 4 + rl; row < Nn; row += gridDim.x * 4) {
        size_t idx = (size_t)row * ELEMF + c;
        float v = fmaf(s2[c], g_sums[idx], t2[c]) + atom[idx];
        outp[idx] = softplusf(v);
    }
}

extern "C" void kernel_launch(void* const* d_in, const int* in_sizes, int n_in,
                              void* d_out, int out_size)
{
    const float* atom   = (const float*)d_in[0];
    const float* nbrfea = (const float*)d_in[1];
    const int*   sIdx   = (const int*)d_in[2];
    const int*   nIdx   = (const int*)d_in[3];
    const float* W      = (const float*)d_in[4];
    const float* b      = (const float*)d_in[5];
    const float* gamma1 = (const float*)d_in[6];
    const float* beta1  = (const float*)d_in[7];
    const float* gamma2 = (const float*)d_in[8];
    const float* beta2  = (const float*)d_in[9];
    float* outp = (float*)d_out;

    const int Nn = in_sizes[0] / ELEMF;
    const int E  = in_sizes[2];
    const int nTiles = (E + 255) / 256;

    const int SMEM_BYTES = 2 * ATILE_BYTES + BTILE_BYTES + 512 + 1024;  // 216576
    cudaFuncSetAttribute(gemm_tc_kernel,
                         cudaFuncAttributeMaxDynamicSharedMemorySize, SMEM_BYTES);
    int sms = 148;
    cudaDeviceGetAttribute(&sms, cudaDevAttrMultiProcessorCount, 0);
    int grid = sms < nTiles ? sms : nTiles;

    const int nAtom = Nn * ELEMF, nEdge = E * NBRF;

    zero_kernel<<<2048, 256>>>(nAtom);
    wconv_kernel<<<(128 * KTOT + 255) / 256, 256>>>(W);
    prep_kernel<<<(nAtom + nEdge + 255) / 256, 256>>>(atom, nbrfea, nAtom, nEdge);
    gemm_tc_kernel<<<grid, 512, SMEM_BYTES>>>(sIdx, nIdx, b, E, nTiles);

    int msg_blocks = (E + 8 * 64 - 1) / (8 * 64);
    msg_segsum_kernel<<<msg_blocks, 256>>>(sIdx, gamma1, beta1, E, 1.f / (float)E);

    stats2_kernel<<<592, 256>>>(Nn);

    int out_blocks = (Nn + 3) / 4;
    out_kernel<<<out_blocks, 256>>>(atom, gamma2, beta2, outp, Nn, 1.f / (float)Nn);
}

// round 9
// speedup vs baseline: 2.6894x; 1.0397x over previous
#include <cuda_runtime.h>
#include <cuda_fp16.h>

#define ELEMF 64
#define NBRF  32
#define COUT  128
#define KTOT  160
#define EPS   1e-5f
#define E_MAX 1600000
#define N_MAX 50000

// fp16 smem rows: 168 halves = 336 bytes (84 banks -> conflict-free LDSM)
#define RSTRIDE_B 336
#define MTILE 192
#define ATILE_BYTES (MTILE * RSTRIDE_B)  // 64512
#define BTILE_BYTES (128 * RSTRIDE_B)    // 43008

// ---------------- scratch (device globals; no allocation allowed) -----------
__device__ __half g_hidden2[(size_t)E_MAX * COUT]; // pre-BN1 hidden (E,128) fp16
__device__ float g_sums[(size_t)N_MAX * ELEMF];    // segment sums (N,64)
__device__ float g_stats1[2 * COUT];
__device__ float g_stats2[2 * ELEMF];
__device__ unsigned char g_Wf[BTILE_BYTES];        // W fp16 [n][k], rows of 336B
__device__ __half g_atomF[(size_t)N_MAX * ELEMF];  // atom table fp16
__device__ __half g_edgeF[(size_t)E_MAX * NBRF];   // edge features fp16

// ---------------- helpers -----------------------------------------------------
__device__ __forceinline__ unsigned smem_u32(const void* p) {
    unsigned a;
    asm("{ .reg .u64 t; cvta.to.shared.u64 t, %1; cvt.u32.u64 %0, t; }"
        : "=r"(a) : "l"(p));
    return a;
}
__device__ __forceinline__ void ldsm4(unsigned addr, unsigned& r0, unsigned& r1,
                                      unsigned& r2, unsigned& r3) {
    asm volatile("ldmatrix.sync.aligned.m8n8.x4.shared.b16 {%0,%1,%2,%3}, [%4];"
                 : "=r"(r0), "=r"(r1), "=r"(r2), "=r"(r3) : "r"(addr));
}
__device__ __forceinline__ void mma16816(float* d, const unsigned* a,
                                         unsigned b0, unsigned b1) {
    asm volatile("mma.sync.aligned.m16n8k16.row.col.f32.f16.f16.f32 "
                 "{%0,%1,%2,%3}, {%4,%5,%6,%7}, {%8,%9}, {%0,%1,%2,%3};"
                 : "+f"(d[0]), "+f"(d[1]), "+f"(d[2]), "+f"(d[3])
                 : "r"(a[0]), "r"(a[1]), "r"(a[2]), "r"(a[3]), "r"(b0), "r"(b1));
}
__device__ __forceinline__ void cp16ca(unsigned dst, const void* src) {
    asm volatile("cp.async.ca.shared.global [%0], [%1], 16;"
                 :: "r"(dst), "l"(src) : "memory");
}
__device__ __forceinline__ void cp16cg(unsigned dst, const void* src) {
    asm volatile("cp.async.cg.shared.global [%0], [%1], 16;"
                 :: "r"(dst), "l"(src) : "memory");
}
#define CP_COMMIT() asm volatile("cp.async.commit_group;" ::: "memory")
#define CP_WAIT(n)  asm volatile("cp.async.wait_group %0;" :: "n"(n) : "memory")

// ---------------- kernels ----------------------------------------------------
// launch 0
__global__ void zero_kernel(int n_sums) {
    int i = blockIdx.x * blockDim.x + threadIdx.x;
    int stride = gridDim.x * blockDim.x;
    for (int j = i; j < n_sums; j += stride) g_sums[j] = 0.f;
    if (i < 2 * COUT)  g_stats1[i] = 0.f;
    if (i < 2 * ELEMF) g_stats2[i] = 0.f;
}

// launch 1: W (160x128 fp32 [k][n]) -> fp16 [n][k] rows of 336B
__global__ void wconv_kernel(const float* __restrict__ W) {
    int i = blockIdx.x * blockDim.x + threadIdx.x;
    if (i >= 128 * KTOT) return;
    int k = i % KTOT;
    int n = i / KTOT;
    *reinterpret_cast<__half*>(g_Wf + n * RSTRIDE_B + k * 2) =
        __float2half_rn(W[k * COUT + n]);
}

// launch 2: atom + edge tables fp32 -> fp16
__global__ void prep_kernel(const float* __restrict__ atom,
                            const float* __restrict__ nbrfea,
                            int nAtom, int nEdge) {
    int i = blockIdx.x * blockDim.x + threadIdx.x;
    if (i < nAtom) g_atomF[i] = __float2half_rn(atom[i]);
    int j = i - nAtom;
    if (j >= 0 && j < nEdge) g_edgeF[j] = __float2half_rn(nbrfea[j]);
}

// Issue the cp.async gather for one tile. 4 threads per row, 5 cp.async each.
__device__ __forceinline__ void issue_gather(
    unsigned abuf, int ebase, int E,
    const int* __restrict__ selfIdx, const int* __restrict__ nbrIdx,
    int gr, int gq)
{
    const int e = ebase + gr;
    if (e < E) {
        const int si = selfIdx[e], ni = nbrIdx[e];
        const unsigned rowA = abuf + gr * RSTRIDE_B;
        const char* sp = reinterpret_cast<const char*>(g_atomF + (size_t)si * ELEMF) + gq * 32;
        const char* np = reinterpret_cast<const char*>(g_atomF + (size_t)ni * ELEMF) + gq * 32;
        cp16ca(rowA + gq * 32,            sp);
        cp16ca(rowA + gq * 32 + 16,       sp + 16);
        cp16ca(rowA + 128 + gq * 32,      np);
        cp16ca(rowA + 128 + gq * 32 + 16, np + 16);
        const char* ep = reinterpret_cast<const char*>(g_edgeF + (size_t)e * NBRF) + gq * 16;
        cp16cg(rowA + 256 + gq * 16, ep);
    }
}

// launch 3 (ncu target): persistent fp16 HMMA gather-GEMM.
// M=192 tile, 768 threads (6m x 4n warps, warp tile m32 x n32),
// double-buffered A via cp.async.
__global__ __launch_bounds__(768, 1) void gemm_tc_kernel(
    const int* __restrict__ selfIdx, const int* __restrict__ nbrIdx,
    const float* __restrict__ bias, int E, int nTiles)
{
    extern __shared__ char smem[];
    const unsigned sbase = smem_u32(smem);

    const int B_OFF    = 2 * ATILE_BYTES;                 // 129024
    const int BIAS_OFF = 2 * ATILE_BYTES + BTILE_BYTES;   // 172032
    const int STAT_OFF = BIAS_OFF + 512;

    const int tid = threadIdx.x, wid = tid >> 5, lane = tid & 31;

    {
        const uint4* src = reinterpret_cast<const uint4*>(g_Wf);
        uint4* dst = reinterpret_cast<uint4*>(smem + B_OFF);
        for (int i = tid; i < BTILE_BYTES / 16; i += 768) dst[i] = src[i];
    }
    if (tid < COUT) reinterpret_cast<float*>(smem + BIAS_OFF)[tid] = bias[tid];
    if (tid < 256)  reinterpret_cast<float*>(smem + STAT_OFF)[tid] = 0.f;
    __syncthreads();

    const int wm = (wid >> 2) * 32;              // 6 m-warps
    const int wn = (wid & 3) * 32;               // 4 n-warps
    const unsigned lane_off = (lane & 15) * RSTRIDE_B + ((lane >> 4) << 4);

    const int cb = wn + 2 * (lane & 3);
    const float* sbias = reinterpret_cast<const float*>(smem + BIAS_OFF);
    const unsigned bbase = sbase + B_OFF + wn * RSTRIDE_B + lane_off;
    float* sstat = reinterpret_cast<float*>(smem + STAT_OFF);

    const int gr = tid >> 2, gq = tid & 3;

    float aS0[4] = {0,0,0,0}, aS1[4] = {0,0,0,0};
    float aQ0[4] = {0,0,0,0}, aQ1[4] = {0,0,0,0};

    int tile = blockIdx.x;
    if (tile < nTiles)
        issue_gather(sbase, tile * MTILE, E, selfIdx, nbrIdx, gr, gq);
    CP_COMMIT();

    int buf = 0;
    for (; tile < nTiles; tile += gridDim.x) {
        const int eb = tile * MTILE;
        const int next = tile + gridDim.x;

        if (next < nTiles) {
            issue_gather(sbase + (buf ^ 1) * ATILE_BYTES, next * MTILE, E,
                         selfIdx, nbrIdx, gr, gq);
            CP_COMMIT();
            CP_WAIT(1);
        } else {
            CP_WAIT(0);
        }
        __syncthreads();

        const unsigned abase = sbase + buf * ATILE_BYTES + wm * RSTRIDE_B + lane_off;
        float d[2][4][4];
#pragma unroll
        for (int i = 0; i < 2; ++i)
#pragma unroll
            for (int j = 0; j < 4; ++j)
#pragma unroll
                for (int q2 = 0; q2 < 4; ++q2) d[i][j][q2] = 0.f;

#pragma unroll
        for (int kk = 0; kk < 10; ++kk) {
            const unsigned kb = kk * 32;
            unsigned a[2][4];
            ldsm4(abase + kb,                  a[0][0], a[0][1], a[0][2], a[0][3]);
            ldsm4(abase + 16 * RSTRIDE_B + kb, a[1][0], a[1][1], a[1][2], a[1][3]);
            unsigned u0, u1, u2, u3, w0, w1, w2, w3;
            ldsm4(bbase + kb,                  u0, u1, u2, u3);
            ldsm4(bbase + 16 * RSTRIDE_B + kb, w0, w1, w2, w3);
#pragma unroll
            for (int i = 0; i < 2; ++i) {
                mma16816(d[i][0], a[i], u0, u2);
                mma16816(d[i][1], a[i], u1, u3);
                mma16816(d[i][2], a[i], w0, w2);
                mma16816(d[i][3], a[i], w1, w3);
            }
        }

        // epilogue before the recycle barrier
#pragma unroll
        for (int i = 0; i < 2; ++i) {
            const int e1 = eb + wm + 16 * i + (lane >> 2);
            const int e2 = e1 + 8;
            const bool v1 = (e1 < E), v2 = (e2 < E);
            __half* out1 = g_hidden2 + (size_t)e1 * COUT + cb;
            __half* out2 = g_hidden2 + (size_t)e2 * COUT + cb;
#pragma unroll
            for (int j = 0; j < 4; ++j) {
                const float b0 = sbias[cb + 8 * j];
                const float b1 = sbias[cb + 8 * j + 1];
                float v00 = d[i][j][0] + b0;
                float v01 = d[i][j][1] + b1;
                float v10 = d[i][j][2] + b0;
                float v11 = d[i][j][3] + b1;
                if (v1) {
                    *reinterpret_cast<__half2*>(out1 + 8 * j) = __floats2half2_rn(v00, v01);
                    aS0[j] += v00; aS1[j] += v01;
                    aQ0[j] += v00 * v00; aQ1[j] += v01 * v01;
                }
                if (v2) {
                    *reinterpret_cast<__half2*>(out2 + 8 * j) = __floats2half2_rn(v10, v11);
                    aS0[j] += v10; aS1[j] += v11;
                    aQ0[j] += v10 * v10; aQ1[j] += v11 * v11;
                }
            }
        }
        __syncthreads();   // LDSM on buf done before next cp.async recycles it
        buf ^= 1;
    }

#pragma unroll
    for (int j = 0; j < 4; ++j) {
#pragma unroll
        for (int ofs = 4; ofs <= 16; ofs <<= 1) {
            aS0[j] += __shfl_xor_sync(0xFFFFFFFF, aS0[j], ofs);
            aS1[j] += __shfl_xor_sync(0xFFFFFFFF, aS1[j], ofs);
            aQ0[j] += __shfl_xor_sync(0xFFFFFFFF, aQ0[j], ofs);
            aQ1[j] += __shfl_xor_sync(0xFFFFFFFF, aQ1[j], ofs);
        }
        if (lane < 4) {
            const int c = wn + 2 * lane + 8 * j;
            atomicAdd(&sstat[c], aS0[j]);
            atomicAdd(&sstat[c + 1], aS1[j]);
            atomicAdd(&sstat[COUT + c], aQ0[j]);
            atomicAdd(&sstat[COUT + c + 1], aQ1[j]);
        }
    }
    __syncthreads();
    if (tid < 256) atomicAdd(&g_stats1[tid], sstat[tid]);
}

// launch 4: BN1 apply + gate + segment-sum, f16x2 math, fp32 accumulation.
__global__ __launch_bounds__(256) void msg_segsum_kernel(
    const int* __restrict__ selfIdx,
    const float* __restrict__ gamma1, const float* __restrict__ beta1,
    int E, float invE)
{
    __shared__ float s1[128], t1[128];
    const int tid = threadIdx.x;
    if (tid < 128) {
        float mean = g_stats1[tid] * invE;
        float var  = g_stats1[128 + tid] * invE - mean * mean;
        float r = rsqrtf(var + EPS);
        float g = gamma1[tid];
        s1[tid] = g * r;
        t1[tid] = beta1[tid] - g * mean * r;
    }
    __syncthreads();

    const int p = tid & 31;
    const int chunk = tid >> 5;
    const int CHUNK = 64;
    long gl = (long)blockIdx.x * 8 + chunk;
    int es = (int)(gl * CHUNK);
    if (es >= E) return;
    int ee = min(es + CHUNK, E);

    const __half2 sf2 = __floats2half2_rn(s1[2*p],      s1[2*p + 1]);
    const __half2 tf2 = __floats2half2_rn(t1[2*p],      t1[2*p + 1]);
    const __half2 sc2 = __floats2half2_rn(s1[64 + 2*p], s1[64 + 2*p + 1]);
    const __half2 tc2 = __floats2half2_rn(t1[64 + 2*p], t1[64 + 2*p + 1]);
    const __half2 one2  = __floats2half2_rn(1.f, 1.f);
    const __half2 zero2 = __floats2half2_rn(0.f, 0.f);

    int cur = selfIdx[es];
    float acc0 = 0.f, acc1 = 0.f;
    for (int e = es; e < ee; ++e) {
        int a = selfIdx[e];
        if (a != cur) {
            atomicAdd(&g_sums[(size_t)cur * ELEMF + 2*p],     acc0);
            atomicAdd(&g_sums[(size_t)cur * ELEMF + 2*p + 1], acc1);
            cur = a; acc0 = 0.f; acc1 = 0.f;
        }
        const __half2* hp = reinterpret_cast<const __half2*>(g_hidden2 + (size_t)e * COUT);
        __half2 f = __hfma2(sf2, hp[p], tf2);
        __half2 g = __hfma2(sc2, hp[32 + p], tc2);
        __half2 sig = h2rcp(__hadd2(one2, h2exp(__hneg2(f))));
        __half2 sp  = __hadd2(__hmax2(g, zero2),
                              h2log(__hadd2(one2, h2exp(__hneg2(__habs2(g))))));
        float2 m = __half22float2(__hmul2(sig, sp));
        acc0 += m.x; acc1 += m.y;
    }
    atomicAdd(&g_sums[(size_t)cur * ELEMF + 2*p],     acc0);
    atomicAdd(&g_sums[(size_t)cur * ELEMF + 2*p + 1], acc1);
}

// launch 5
__global__ __launch_bounds__(256) void stats2_kernel(int Nn) {
    __shared__ float rs[4][64];
    __shared__ float rq[4][64];
    const int tid = threadIdx.x;
    const int c = tid & 63, rl = tid >> 6;
    float s = 0.f, q = 0.f;
    for (int row = blockIdx.x * 4 + rl; row < Nn; row += gridDim.x * 4) {
        float v = g_sums[(size_t)row * ELEMF + c];
        s += v; q += v * v;
    }
    rs[rl][c] = s; rq[rl][c] = q;
    __syncthreads();
    if (tid < 64) {
        float ss = 0.f, qq = 0.f;
#pragma unroll
        for (int r = 0; r < 4; ++r) { ss += rs[r][tid]; qq += rq[r][tid]; }
        atomicAdd(&g_stats2[tid], ss);
        atomicAdd(&g_stats2[64 + tid], qq);
    }
}

// launch 6
__device__ __forceinline__ float softplusf(float x) {
    return (x > 15.f) ? x : log1pf(expf(x));
}
__global__ __launch_bounds__(256) void out_kernel(
    const float* __restrict__ atom,
    const float* __restrict__ gamma2, const float* __restrict__ beta2,
    float* __restrict__ outp, int Nn, float invN)
{
    __shared__ float s2[64], t2[64];
    const int tid = threadIdx.x;
    if (tid < 64) {
        float mean = g_stats2[tid] * invN;
        float var  = g_stats2[64 + tid] * invN - mean * mean;
        float r = rsqrtf(var + EPS);
        float g = gamma2[tid];
        s2[tid] = g * r;
        t2[tid] = beta2[tid] - g * mean * r;
    }
    __syncthreads();
    const int c = tid & 63, rl = tid >> 6;
    for (int row = blockIdx.x * 4 + rl; row < Nn; row += gridDim.x * 4) {
        size_t idx = (size_t)row * ELEMF + c;
        float v = fmaf(s2[c], g_sums[idx], t2[c]) + atom[idx];
        outp[idx] = softplusf(v);
    }
}

extern "C" void kernel_launch(void* const* d_in, const int* in_sizes, int n_in,
                              void* d_out, int out_size)
{
    const float* atom   = (const float*)d_in[0];
    const float* nbrfea = (const float*)d_in[1];
    const int*   sIdx   = (const int*)d_in[2];
    const int*   nIdx   = (const int*)d_in[3];
    const float* W      = (const float*)d_in[4];
    const float* b      = (const float*)d_in[5];
    const float* gamma1 = (const float*)d_in[6];
    const float* beta1  = (const float*)d_in[7];
    const float* gamma2 = (const float*)d_in[8];
    const float* beta2  = (const float*)d_in[9];
    float* outp = (float*)d_out;

    const int Nn = in_sizes[0] / ELEMF;
    const int E  = in_sizes[2];
    const int nTiles = (E + MTILE - 1) / MTILE;

    const int SMEM_BYTES = 2 * ATILE_BYTES + BTILE_BYTES + 512 + 1024;  // 173568
    cudaFuncSetAttribute(gemm_tc_kernel,
                         cudaFuncAttributeMaxDynamicSharedMemorySize, SMEM_BYTES);
    int sms = 148;
    cudaDeviceGetAttribute(&sms, cudaDevAttrMultiProcessorCount, 0);
    int grid = sms < nTiles ? sms : nTiles;

    const int nAtom = Nn * ELEMF, nEdge = E * NBRF;

    zero_kernel<<<2048, 256>>>(nAtom);
    wconv_kernel<<<(128 * KTOT + 255) / 256, 256>>>(W);
    prep_kernel<<<(nAtom + nEdge + 255) / 256, 256>>>(atom, nbrfea, nAtom, nEdge);
    gemm_tc_kernel<<<grid, 768, SMEM_BYTES>>>(sIdx, nIdx, b, E, nTiles);

    int msg_blocks = (E + 8 * 64 - 1) / (8 * 64);
    msg_segsum_kernel<<<msg_blocks, 256>>>(sIdx, gamma1, beta1, E, 1.f / (float)E);

    stats2_kernel<<<592, 256>>>(Nn);

    int out_blocks = (Nn + 3) / 4;
    out_kernel<<<out_blocks, 256>>>(atom, gamma2, beta2, outp, Nn, 1.f / (float)Nn);
}